// round 11
// baseline (speedup 1.0000x reference)
#include <cuda_runtime.h>
#include <cuda_fp16.h>

// Problem constants
#define B_    2
#define S_    1024
#define D_    1024
#define H_    16
#define DH_   64
#define BH_   (B_*H_)      // 32
#define ROWS_ (B_*S_)      // 2048
#define SS_   (S_*S_)      // 1048576

#define NEG_INF __int_as_float(0xff800000)

// ---------------------------------------------------------------------------
// Device-global scratch (allocation-free rule). fp16 operands split hi/lo.
// ---------------------------------------------------------------------------
__device__ __align__(16) __half g_xh [ROWS_*D_], g_xl [ROWS_*D_];
__device__ __align__(16) __half g_relh[ROWS_*D_], g_rell[ROWS_*D_];
__device__ __align__(16) __half g_Wh[6][D_*D_],  g_Wl[6][D_*D_]; // q,k,v,qr,kr,c

__device__ __align__(16) __half g_qh [BH_*S_*DH_], g_ql [BH_*S_*DH_];
__device__ __align__(16) __half g_kh [BH_*S_*DH_], g_kl [BH_*S_*DH_];
__device__ __align__(16) __half g_qrh[BH_*S_*DH_], g_qrl[BH_*S_*DH_];
__device__ __align__(16) __half g_krh[BH_*S_*DH_], g_krl[BH_*S_*DH_];
__device__ __align__(16) __half g_vTh[BH_*DH_*S_], g_vTl[BH_*DH_*S_]; // [bh][d][s]

__device__ __align__(16) float g_c2c[BH_*SS_];          // c2c scores / combined
__device__ __align__(16) __half g_c2ph[BH_*SS_];        // c2p_att (fp16)
__device__ __align__(16) __half g_p2ch[BH_*SS_];        // p2c_att (fp16)

__device__ __align__(16) __half g_ph[BH_*SS_], g_pl[BH_*SS_];     // probs
__device__ __align__(16) __half g_ctxh[ROWS_*D_], g_ctxl[ROWS_*D_];

// ---------------------------------------------------------------------------
// Helpers
// ---------------------------------------------------------------------------
__device__ __forceinline__ unsigned smem_u32(const void* p) {
    unsigned a;
    asm("{ .reg .u64 t; cvta.to.shared.u64 t, %1; cvt.u32.u64 %0, t; }"
        : "=r"(a) : "l"(p));
    return a;
}

__device__ __forceinline__ void ldsm4(unsigned r[4], unsigned a) {
    asm volatile("ldmatrix.sync.aligned.m8n8.x4.shared.b16 {%0,%1,%2,%3}, [%4];"
        : "=r"(r[0]), "=r"(r[1]), "=r"(r[2]), "=r"(r[3]) : "r"(a));
}

__device__ __forceinline__ void mma_f16(float c[4], const unsigned a[4],
                                        unsigned b0, unsigned b1) {
    asm volatile(
        "mma.sync.aligned.m16n8k16.row.col.f32.f16.f16.f32 "
        "{%0,%1,%2,%3}, {%4,%5,%6,%7}, {%8,%9}, {%0,%1,%2,%3};"
        : "+f"(c[0]), "+f"(c[1]), "+f"(c[2]), "+f"(c[3])
        : "r"(a[0]), "r"(a[1]), "r"(a[2]), "r"(a[3]), "r"(b0), "r"(b1));
}

__device__ __forceinline__ void split1(float a, __half& h, __half& l) {
    h = __float2half_rn(a);
    l = __float2half_rn(a - __half2float(h));
}

__device__ __forceinline__ void cp16(unsigned s, const void* g) {
    asm volatile("cp.async.cg.shared.global [%0], [%1], 16;" :: "r"(s), "l"(g));
}
#define CP_COMMIT() asm volatile("cp.async.commit_group;" ::: "memory")
#define CP_WAIT0()  asm volatile("cp.async.wait_group 0;" ::: "memory")
#define CP_WAIT1()  asm volatile("cp.async.wait_group 1;" ::: "memory")

// ---------------------------------------------------------------------------
// Operand conversion: fp32 -> hi/lo fp16, all 8 tensors in one launch.
// ---------------------------------------------------------------------------
__global__ __launch_bounds__(256) void convert_all(
    const float* __restrict__ x,  const float* __restrict__ rel,
    const float* __restrict__ W0, const float* __restrict__ W1,
    const float* __restrict__ W2, const float* __restrict__ W3,
    const float* __restrict__ W4, const float* __restrict__ W5)
{
    const int i = blockIdx.x * 256 + threadIdx.x;   // grid covers 2621440
    const float* src; __half *Dh, *Dl; int off;
    if (i < 1048576) {
        if (i < 524288) { src = x;   Dh = g_xh;   Dl = g_xl;   off = i; }
        else            { src = rel; Dh = g_relh; Dl = g_rell; off = i - 524288; }
    } else {
        const int w = (i - 1048576) >> 18;
        off = (i - 1048576) & 262143;
        switch (w) {
            case 0:  src = W0; break; case 1: src = W1; break;
            case 2:  src = W2; break; case 3: src = W3; break;
            case 4:  src = W4; break; default: src = W5; break;
        }
        Dh = g_Wh[w]; Dl = g_Wl[w];
    }
    float4 v = ((const float4*)src)[off];
    __half h[4], l[4];
    split1(v.x, h[0], l[0]); split1(v.y, h[1], l[1]);
    split1(v.z, h[2], l[2]); split1(v.w, h[3], l[3]);
    *(uint2*)(Dh + off * 4) = *(uint2*)h;
    *(uint2*)(Dl + off * 4) = *(uint2*)l;
}

// ---------------------------------------------------------------------------
// HMMA GEMM core, cp.async double-buffered. PASSES=3: Ah*Bh+Ah*Bl+Al*Bh.
// PASSES=2: Ah*Bh+Ah*Bl (A-lo neither staged nor loaded).
// ---------------------------------------------------------------------------
template<int NT, int PASSES>
__device__ __forceinline__ void gemm_core(
    const __half* __restrict__ Ah, const __half* __restrict__ Al, int lda,
    const __half* __restrict__ Bh, const __half* __restrict__ Bl, int ldb,
    int ktiles, float acc[2][NT][4])
{
    extern __shared__ __align__(16) __half dyn[];
    constexpr int ABYTES = 128 * 40 * 2;        // 10240
    constexpr int BBYTES = NT * 16 * 40 * 2;
    constexpr int STGB   = 2 * ABYTES + 2 * BBYTES;

    const int tid  = threadIdx.x;
    const int lane = tid & 31;
    const int wid  = tid >> 5;
    const int wm   = wid & 3;
    const int wn   = wid >> 2;
    const unsigned uB = smem_u32(dyn);

    const unsigned aoff = (unsigned)((wm * 32 + (lane & 15)) * 80 + ((lane >> 4) << 4));
    const unsigned boff = (unsigned)((wn * (NT * 8) + (lane & 7) + ((lane >> 4) << 3)) * 80
                                     + (((lane >> 3) & 1) << 4));

    auto issue = [&](int st, int kt) {
        const int kb = kt * 32;
        const unsigned sbase = uB + st * STGB;
#pragma unroll
        for (int s = 0; s < 2; s++) {                 // A: 512 chunks
            int ch = s * 256 + tid;
            int r = ch >> 2, ks = ch & 3;
            unsigned o = (unsigned)(r * 80 + ks * 16);
            cp16(sbase + o, Ah + r * lda + kb + ks * 8);
            if (PASSES == 3)
                cp16(sbase + ABYTES + o, Al + r * lda + kb + ks * 8);
        }
#pragma unroll
        for (int s = 0; s < NT / 4; s++) {            // B: NT*64 chunks
            int ch = s * 256 + tid;
            int r = ch >> 2, ks = ch & 3;
            unsigned o = (unsigned)(r * 80 + ks * 16);
            cp16(sbase + 2 * ABYTES + o, Bh + r * ldb + kb + ks * 8);
            cp16(sbase + 2 * ABYTES + BBYTES + o, Bl + r * ldb + kb + ks * 8);
        }
        CP_COMMIT();
    };

    issue(0, 0);

    for (int kt = 0; kt < ktiles; kt++) {
        const int st = kt & 1;
        if (kt + 1 < ktiles) { issue(st ^ 1, kt + 1); CP_WAIT1(); }
        else                 { CP_WAIT0(); }
        __syncthreads();

        const unsigned sbase = uB + st * STGB;
        const unsigned uAh = sbase, uAl = sbase + ABYTES;
        const unsigned uBh = sbase + 2 * ABYTES, uBl = uBh + BBYTES;

#pragma unroll
        for (int ks = 0; ks < 2; ks++) {
            unsigned ah[2][4], al[2][4];
#pragma unroll
            for (int mt = 0; mt < 2; mt++) {
                unsigned o = aoff + mt * 16 * 80 + ks * 32;
                ldsm4(ah[mt], uAh + o);
                if (PASSES == 3) ldsm4(al[mt], uAl + o);
            }
#pragma unroll
            for (int np = 0; np < NT / 2; np++) {
                unsigned o = boff + np * 16 * 80 + ks * 32;
                unsigned bh[4], bl[4];
                ldsm4(bh, uBh + o);
                ldsm4(bl, uBl + o);
#pragma unroll
                for (int mt = 0; mt < 2; mt++) {
#pragma unroll
                    for (int sub = 0; sub < 2; sub++) {
                        float* c = acc[mt][np * 2 + sub];
                        mma_f16(c, ah[mt], bh[sub * 2], bh[sub * 2 + 1]);
                        mma_f16(c, ah[mt], bl[sub * 2], bl[sub * 2 + 1]);
                        if (PASSES == 3)
                            mma_f16(c, al[mt], bh[sub * 2], bh[sub * 2 + 1]);
                    }
                }
            }
        }
        __syncthreads();
    }
}

#define SMEM_NT8 (2 * (2 * 128 * 40 * 2 + 2 * 8 * 16 * 40 * 2))   // 81920
#define SMEM_NT4 (2 * (2 * 128 * 40 * 2 + 2 * 4 * 16 * 40 * 2))   // 61440

// ---------------------------------------------------------------------------
// Kernel 1: projections. z: 0=Q 1=K 2=V 3=QR 4=KR.  out head-major hi/lo fp16.
// ---------------------------------------------------------------------------
__global__ __launch_bounds__(256) void proj_mma(
    const float* __restrict__ bq, const float* __restrict__ bk,
    const float* __restrict__ bv, const float* __restrict__ bqr,
    const float* __restrict__ bkr)
{
    const int z = blockIdx.z;
    const __half *Ah, *Al;
    if (z < 3) { Ah = g_xh; Al = g_xl; } else { Ah = g_relh; Al = g_rell; }
    const __half* Bh = g_Wh[z];
    const __half* Bl = g_Wl[z];

    __half *Dh, *Dl; const float* bias;
    switch (z) {
        case 0:  Dh = g_qh;  Dl = g_ql;  bias = bq;  break;
        case 1:  Dh = g_kh;  Dl = g_kl;  bias = bk;  break;
        case 2:  Dh = g_vTh; Dl = g_vTl; bias = bv;  break;
        case 3:  Dh = g_qrh; Dl = g_qrl; bias = bqr; break;
        default: Dh = g_krh; Dl = g_krl; bias = bkr; break;
    }

    const int brow = blockIdx.y * 128;
    const int bcol = blockIdx.x * 128;

    float acc[2][8][4] = {};
    gemm_core<8, 3>(Ah + brow * D_, Al + brow * D_, D_,
                    Bh + bcol * D_, Bl + bcol * D_, D_, 32, acc);

    const int lane = threadIdx.x & 31, wid = threadIdx.x >> 5;
    const int wm = wid & 3, wn = wid >> 2;
    const bool vtrans = (z == 2);

#pragma unroll
    for (int mt = 0; mt < 2; mt++) {
#pragma unroll
        for (int nt = 0; nt < 8; nt++) {
            const int n = bcol + wn * 64 + nt * 8 + (lane & 3) * 2;
            const int h = n >> 6, d = n & 63;
            const float b0 = __ldg(&bias[n]), b1 = __ldg(&bias[n + 1]);
#pragma unroll
            for (int half = 0; half < 2; half++) {
                const int m = brow + wm * 32 + mt * 16 + (lane >> 2) + half * 8;
                const int bb = m >> 10, s = m & (S_ - 1);
                float v0 = acc[mt][nt][half * 2 + 0] + b0;
                float v1 = acc[mt][nt][half * 2 + 1] + b1;
                __half h0, l0, h1, l1;
                split1(v0, h0, l0); split1(v1, h1, l1);
                if (!vtrans) {
                    const int idx = ((bb * H_ + h) * S_ + s) * DH_ + d;
                    __half2 ph; ph.x = h0; ph.y = h1;
                    __half2 pl; pl.x = l0; pl.y = l1;
                    *(__half2*)(Dh + idx) = ph;
                    *(__half2*)(Dl + idx) = pl;
                } else {
                    const int idx = ((bb * H_ + h) * DH_ + d) * S_ + s;
                    Dh[idx] = h0; Dh[idx + S_] = h1;
                    Dl[idx] = l0; Dl[idx + S_] = l1;
                }
            }
        }
    }
}

// ---------------------------------------------------------------------------
// Kernel 2: score GEMMs, 2-pass fp16x2. z = bh*3 + which.  K = 64.
// which==0 (c2c): fp32 out.  which==1/2 (c2p/p2c): single-fp16 out.
// ---------------------------------------------------------------------------
__global__ __launch_bounds__(256) void scores_mma()
{
    const int z = blockIdx.z;
    const int bh = z / 3;
    const int which = z - bh * 3;
    const int ho = bh * S_ * DH_;

    const __half *Ah, *Al, *Bh, *Bl;
    float* Oc = nullptr; __half* Ob = nullptr;
    if (which == 0)      { Ah = g_qh + ho;  Al = g_ql + ho;  Bh = g_kh + ho;  Bl = g_kl + ho;  Oc = g_c2c + bh * SS_; }
    else if (which == 1) { Ah = g_qh + ho;  Al = g_ql + ho;  Bh = g_krh + ho; Bl = g_krl + ho; Ob = g_c2ph + bh * SS_; }
    else                 { Ah = g_qrh + ho; Al = g_qrl + ho; Bh = g_kh + ho;  Bl = g_kl + ho;  Ob = g_p2ch + bh * SS_; }

    const int brow = blockIdx.y * 128;
    const int bcol = blockIdx.x * 128;

    float acc[2][8][4] = {};
    gemm_core<8, 2>(Ah + brow * DH_, Al + brow * DH_, DH_,
                    Bh + bcol * DH_, Bl + bcol * DH_, DH_, 2, acc);

    const int lane = threadIdx.x & 31, wid = threadIdx.x >> 5;
    const int wm = wid & 3, wn = wid >> 2;
#pragma unroll
    for (int mt = 0; mt < 2; mt++) {
#pragma unroll
        for (int nt = 0; nt < 8; nt++) {
            const int n = bcol + wn * 64 + nt * 8 + (lane & 3) * 2;
#pragma unroll
            for (int half = 0; half < 2; half++) {
                const int m = brow + wm * 32 + mt * 16 + (lane >> 2) + half * 8;
                const float v0 = acc[mt][nt][half * 2];
                const float v1 = acc[mt][nt][half * 2 + 1];
                if (which == 0) {
                    *(float2*)(Oc + m * S_ + n) = make_float2(v0, v1);
                } else {
                    __half2 p;
                    p.x = __float2half_rn(v0);
                    p.y = __float2half_rn(v1);
                    *(__half2*)(Ob + m * S_ + n) = p;
                }
            }
        }
    }
}

// ---------------------------------------------------------------------------
// Combine: 32 x 128 tile, exact-window band staging from fp16 sources,
// float4 main loop.
// scores = (c2c + c2p[i, p(i,j)] + p2c[p(i,j), j]) / scale, + mask
// p(i,j) = clamp(i - j + 512, 0, 1023).
// c2pS[il][w]: w = 127 - jl  -> c2p[i0+il][clamp(P0+il-127+w)]
// p2cS[t][il]: t = il - jl + 127 -> p2c[clamp(P0-127+t)][j0 + il + 127 - t]
// ---------------------------------------------------------------------------
__global__ __launch_bounds__(256) void combine_kernel(const int* __restrict__ mask)
{
    const int bh = blockIdx.z;
    const int b  = bh >> 4;
    const int i0 = blockIdx.y * 32;
    const int j0 = blockIdx.x * 128;
    const int off = bh * SS_;
    const int P0 = i0 - j0 + 512;

    __shared__ float c2pS[32][132];   // pitch 132
    __shared__ float p2cS[159][33];   // pitch 33

    const int tid = threadIdx.x;

    // Stage c2p: row il needs p in [P0+il-127, P0+il]; scalar fp16, coalesced.
    {
        const int row0 = tid >> 5;          // 0..7
        const int w0   = (tid & 31) * 4;    // 0..124 step 4
#pragma unroll
        for (int rr = 0; rr < 4; rr++) {
            const int row = row0 + rr * 8;
            const __half* src = g_c2ph + off + (i0 + row) * S_;
            const int pb = P0 + row - 127 + w0;
            float4 v;
            v.x = __half2float(src[min(max(pb + 0, 0), S_ - 1)]);
            v.y = __half2float(src[min(max(pb + 1, 0), S_ - 1)]);
            v.z = __half2float(src[min(max(pb + 2, 0), S_ - 1)]);
            v.w = __half2float(src[min(max(pb + 3, 0), S_ - 1)]);
            *(float4*)&c2pS[row][w0] = v;
        }
    }

    // Stage p2c: 159 t-rows x 32 slots, coalesced 32-wide per t-row (fp16).
#pragma unroll
    for (int it = 0; it < 20; it++) {
        const int seg = it * 256 + tid;
        if (seg < 159 * 32) {
            const int t  = seg >> 5;
            const int il = seg & 31;
            const int p  = min(max(P0 - 127 + t, 0), S_ - 1);
            const int j  = min(max(j0 + il + 127 - t, 0), S_ - 1);
            p2cS[t][il] = __half2float(g_p2ch[off + p * S_ + j]);
        }
    }
    __syncthreads();

    const float invScale = 0.07216878364870323f;  // 1/sqrt(3*64)
    const int il = tid >> 3;
    const int jc = (tid & 7) * 4;
    float* crow = g_c2c + off + (i0 + il) * S_ + j0;
    const int* mrow = mask + b * S_ + j0;

#pragma unroll
    for (int pass = 0; pass < 4; pass++) {
        const int jl = jc + pass * 32;
        float4 c  = *(const float4*)(crow + jl);
        float4 cp = *(const float4*)&c2pS[il][124 - jl];   // reversed order
        const int tb = il - jl + 127;
        const float q0 = p2cS[tb    ][il];
        const float q1 = p2cS[tb - 1][il];
        const float q2 = p2cS[tb - 2][il];
        const float q3 = p2cS[tb - 3][il];
        const int4 mk = *(const int4*)(mrow + jl);

        float4 r;
        r.x = mk.x ? NEG_INF : (c.x + cp.w + q0) * invScale;
        r.y = mk.y ? NEG_INF : (c.y + cp.z + q1) * invScale;
        r.z = mk.z ? NEG_INF : (c.z + cp.y + q2) * invScale;
        r.w = mk.w ? NEG_INF : (c.w + cp.x + q3) * invScale;
        *(float4*)(crow + jl) = r;
    }
}

// ---------------------------------------------------------------------------
// Softmax: read fp32 scores, write probs as hi/lo fp16.
// ---------------------------------------------------------------------------
__global__ __launch_bounds__(256) void softmax_kernel()
{
    const int rowoff = blockIdx.y * SS_ + blockIdx.x * S_;
    const float* p = g_c2c + rowoff;
    const int tid = threadIdx.x;

    float4 v = *(const float4*)(p + tid * 4);
    float mx = fmaxf(fmaxf(v.x, v.y), fmaxf(v.z, v.w));
#pragma unroll
    for (int o = 16; o > 0; o >>= 1)
        mx = fmaxf(mx, __shfl_xor_sync(0xffffffffu, mx, o));

    __shared__ float smax[8], ssum[8];
    if ((tid & 31) == 0) smax[tid >> 5] = mx;
    __syncthreads();
    mx = fmaxf(fmaxf(fmaxf(smax[0], smax[1]), fmaxf(smax[2], smax[3])),
               fmaxf(fmaxf(smax[4], smax[5]), fmaxf(smax[6], smax[7])));

    v.x = __expf(v.x - mx);
    v.y = __expf(v.y - mx);
    v.z = __expf(v.z - mx);
    v.w = __expf(v.w - mx);
    float s = v.x + v.y + v.z + v.w;
#pragma unroll
    for (int o = 16; o > 0; o >>= 1)
        s += __shfl_xor_sync(0xffffffffu, s, o);
    if ((tid & 31) == 0) ssum[tid >> 5] = s;
    __syncthreads();
    s = ssum[0] + ssum[1] + ssum[2] + ssum[3] +
        ssum[4] + ssum[5] + ssum[6] + ssum[7];

    const float inv = 1.0f / s;
    v.x *= inv; v.y *= inv; v.z *= inv; v.w *= inv;

    __half h[4], l[4];
    split1(v.x, h[0], l[0]); split1(v.y, h[1], l[1]);
    split1(v.z, h[2], l[2]); split1(v.w, h[3], l[3]);
    *(uint2*)(g_ph + rowoff + tid * 4) = *(uint2*)h;
    *(uint2*)(g_pl + rowoff + tid * 4) = *(uint2*)l;
}

// ---------------------------------------------------------------------------
// Kernel 3: attn @ V  (probs 1024x1024 @ V 1024x64 per bh) -> ctx hi/lo fp16
// ---------------------------------------------------------------------------
__global__ __launch_bounds__(256) void av_mma()
{
    const int bh = blockIdx.y;
    const int i0 = blockIdx.x * 128;
    const __half* Ah = g_ph + bh * SS_ + i0 * S_;
    const __half* Al = g_pl + bh * SS_ + i0 * S_;
    const __half* Bh = g_vTh + bh * DH_ * S_;
    const __half* Bl = g_vTl + bh * DH_ * S_;

    float acc[2][4][4] = {};
    gemm_core<4, 3>(Ah, Al, S_, Bh, Bl, S_, 32, acc);

    const int lane = threadIdx.x & 31, wid = threadIdx.x >> 5;
    const int wm = wid & 3, wn = wid >> 2;
    const int b = bh >> 4, h = bh & 15;

#pragma unroll
    for (int mt = 0; mt < 2; mt++) {
#pragma unroll
        for (int nt = 0; nt < 4; nt++) {
            const int d = wn * 32 + nt * 8 + (lane & 3) * 2;
#pragma unroll
            for (int half = 0; half < 2; half++) {
                const int s = i0 + wm * 32 + mt * 16 + (lane >> 2) + half * 8;
                const int idx = (b * S_ + s) * D_ + h * DH_ + d;
                float v0 = acc[mt][nt][half * 2 + 0];
                float v1 = acc[mt][nt][half * 2 + 1];
                __half h0, l0, h1, l1;
                split1(v0, h0, l0); split1(v1, h1, l1);
                __half2 ph; ph.x = h0; ph.y = h1;
                __half2 pl; pl.x = l0; pl.y = l1;
                *(__half2*)(g_ctxh + idx) = ph;
                *(__half2*)(g_ctxl + idx) = pl;
            }
        }
    }
}

// ---------------------------------------------------------------------------
// Kernel 4: output projection out = ctx @ Wc^T + bc  (fp32 out)
// ---------------------------------------------------------------------------
__global__ __launch_bounds__(256) void final_mma(
    const float* __restrict__ bc, float* __restrict__ out)
{
    const int brow = blockIdx.y * 128;
    const int bcol = blockIdx.x * 128;

    float acc[2][8][4] = {};
    gemm_core<8, 3>(g_ctxh + brow * D_, g_ctxl + brow * D_, D_,
                    g_Wh[5] + bcol * D_, g_Wl[5] + bcol * D_, D_, 32, acc);

    const int lane = threadIdx.x & 31, wid = threadIdx.x >> 5;
    const int wm = wid & 3, wn = wid >> 2;
#pragma unroll
    for (int mt = 0; mt < 2; mt++) {
#pragma unroll
        for (int nt = 0; nt < 8; nt++) {
            const int n = bcol + wn * 64 + nt * 8 + (lane & 3) * 2;
            const float b0 = __ldg(&bc[n]), b1 = __ldg(&bc[n + 1]);
#pragma unroll
            for (int half = 0; half < 2; half++) {
                const int m = brow + wm * 32 + mt * 16 + (lane >> 2) + half * 8;
                *(float2*)(out + m * D_ + n) =
                    make_float2(acc[mt][nt][half * 2] + b0,
                                acc[mt][nt][half * 2 + 1] + b1);
            }
        }
    }
}

// ---------------------------------------------------------------------------
// Launch
// ---------------------------------------------------------------------------
extern "C" void kernel_launch(void* const* d_in, const int* in_sizes, int n_in,
                              void* d_out, int out_size)
{
    const float* x    = (const float*)d_in[0];
    const float* rel  = (const float*)d_in[1];
    const int*   mask = (const int*)  d_in[2];
    const float* Wq   = (const float*)d_in[3];
    const float* bq   = (const float*)d_in[4];
    const float* Wk   = (const float*)d_in[5];
    const float* bk   = (const float*)d_in[6];
    const float* Wv   = (const float*)d_in[7];
    const float* bv   = (const float*)d_in[8];
    const float* Wqr  = (const float*)d_in[9];
    const float* bqr  = (const float*)d_in[10];
    const float* Wkr  = (const float*)d_in[11];
    const float* bkr  = (const float*)d_in[12];
    const float* Wc   = (const float*)d_in[13];
    const float* bc   = (const float*)d_in[14];
    float* out = (float*)d_out;

    static int attr_done = 0;
    if (!attr_done) {
        cudaFuncSetAttribute(proj_mma,   cudaFuncAttributeMaxDynamicSharedMemorySize, SMEM_NT8);
        cudaFuncSetAttribute(scores_mma, cudaFuncAttributeMaxDynamicSharedMemorySize, SMEM_NT8);
        cudaFuncSetAttribute(av_mma,     cudaFuncAttributeMaxDynamicSharedMemorySize, SMEM_NT4);
        cudaFuncSetAttribute(final_mma,  cudaFuncAttributeMaxDynamicSharedMemorySize, SMEM_NT8);
        attr_done = 1;
    }

    // 0. Split fp32 operands into hi/lo fp16 (single launch)
    convert_all<<<2621440 / 256, 256>>>(x, rel, Wq, Wk, Wv, Wqr, Wkr, Wc);

    // 1. Projections (HMMA fp16x3, z-fused)
    proj_mma<<<dim3(D_ / 128, ROWS_ / 128, 5), 256, SMEM_NT8>>>(bq, bk, bv, bqr, bkr);

    // 2. Score GEMMs (fp16x2 2-pass; c2c fp32, c2p/p2c fp16)
    scores_mma<<<dim3(S_ / 128, S_ / 128, BH_ * 3), 256, SMEM_NT8>>>();

    // 3. Banded gather + sum + scale + mask (fp16 band inputs)
    combine_kernel<<<dim3(S_ / 128, S_ / 32, BH_), 256>>>(mask);

    // 4. Softmax -> probs hi/lo fp16
    softmax_kernel<<<dim3(S_, BH_), 256>>>();

    // 5. attn @ V -> ctx hi/lo fp16 (fp16x3)
    av_mma<<<dim3(S_ / 128, BH_), 256, SMEM_NT4>>>();

    // 6. Output projection (fp16x3)
    final_mma<<<dim3(D_ / 128, ROWS_ / 128), 256, SMEM_NT8>>>(bc, out);
}

// round 12
// speedup vs baseline: 1.0347x; 1.0347x over previous
#include <cuda_runtime.h>
#include <cuda_bf16.h>

// Problem constants
#define B_    2
#define S_    1024
#define D_    1024
#define H_    16
#define DH_   64
#define BH_   (B_*H_)      // 32
#define ROWS_ (B_*S_)      // 2048
#define SS_   (S_*S_)      // 1048576

#define NEG_INF __int_as_float(0xff800000)

// ---------------------------------------------------------------------------
// Device-global scratch (allocation-free rule). bf16 operands split hi/lo.
// ---------------------------------------------------------------------------
__device__ __align__(16) __nv_bfloat16 g_xh [ROWS_*D_], g_xl [ROWS_*D_];
__device__ __align__(16) __nv_bfloat16 g_relh[ROWS_*D_], g_rell[ROWS_*D_];
__device__ __align__(16) __nv_bfloat16 g_Wh[6][D_*D_],  g_Wl[6][D_*D_]; // q,k,v,qr,kr,c

__device__ __align__(16) __nv_bfloat16 g_qh [BH_*S_*DH_], g_ql [BH_*S_*DH_];
__device__ __align__(16) __nv_bfloat16 g_kh [BH_*S_*DH_], g_kl [BH_*S_*DH_];
__device__ __align__(16) __nv_bfloat16 g_qrh[BH_*S_*DH_], g_qrl[BH_*S_*DH_];
__device__ __align__(16) __nv_bfloat16 g_krh[BH_*S_*DH_], g_krl[BH_*S_*DH_];
__device__ __align__(16) __nv_bfloat16 g_vTh[BH_*DH_*S_], g_vTl[BH_*DH_*S_]; // [bh][d][s]

__device__ __align__(16) float g_c2c[BH_*SS_];                 // c2c scores / combined
__device__ __align__(16) __nv_bfloat16 g_c2pb[BH_*SS_];        // c2p_att (bf16)
__device__ __align__(16) __nv_bfloat16 g_p2cb[BH_*SS_];        // p2c_att (bf16)

__device__ __align__(16) __nv_bfloat16 g_ph[BH_*SS_], g_pl[BH_*SS_];     // probs
__device__ __align__(16) __nv_bfloat16 g_ctxh[ROWS_*D_], g_ctxl[ROWS_*D_];

// ---------------------------------------------------------------------------
// Helpers
// ---------------------------------------------------------------------------
__device__ __forceinline__ unsigned smem_u32(const void* p) {
    unsigned a;
    asm("{ .reg .u64 t; cvta.to.shared.u64 t, %1; cvt.u32.u64 %0, t; }"
        : "=r"(a) : "l"(p));
    return a;
}

__device__ __forceinline__ void ldsm4(unsigned r[4], unsigned a) {
    asm volatile("ldmatrix.sync.aligned.m8n8.x4.shared.b16 {%0,%1,%2,%3}, [%4];"
        : "=r"(r[0]), "=r"(r[1]), "=r"(r[2]), "=r"(r[3]) : "r"(a));
}

__device__ __forceinline__ void mma_bf16(float c[4], const unsigned a[4],
                                         unsigned b0, unsigned b1) {
    asm volatile(
        "mma.sync.aligned.m16n8k16.row.col.f32.bf16.bf16.f32 "
        "{%0,%1,%2,%3}, {%4,%5,%6,%7}, {%8,%9}, {%0,%1,%2,%3};"
        : "+f"(c[0]), "+f"(c[1]), "+f"(c[2]), "+f"(c[3])
        : "r"(a[0]), "r"(a[1]), "r"(a[2]), "r"(a[3]), "r"(b0), "r"(b1));
}

__device__ __forceinline__ void split1(float a, __nv_bfloat16& h, __nv_bfloat16& l) {
    h = __float2bfloat16(a);
    l = __float2bfloat16(a - __bfloat162float(h));
}

__device__ __forceinline__ void cp16(unsigned s, const void* g) {
    asm volatile("cp.async.cg.shared.global [%0], [%1], 16;" :: "r"(s), "l"(g));
}
#define CP_COMMIT() asm volatile("cp.async.commit_group;" ::: "memory")
#define CP_WAIT0()  asm volatile("cp.async.wait_group 0;" ::: "memory")
#define CP_WAIT1()  asm volatile("cp.async.wait_group 1;" ::: "memory")
#define CP_WAIT2()  asm volatile("cp.async.wait_group 2;" ::: "memory")

// ---------------------------------------------------------------------------
// Operand conversion: fp32 -> hi/lo bf16. 3 launches (phase 0: x+rel,
// phase 1: W0-2, phase 2: W3-5) so proj_mma lands in ncu's capture slot.
// ---------------------------------------------------------------------------
__global__ __launch_bounds__(256) void convert_all(
    const float* __restrict__ x,  const float* __restrict__ rel,
    const float* __restrict__ W0, const float* __restrict__ W1,
    const float* __restrict__ W2, const float* __restrict__ W3,
    const float* __restrict__ W4, const float* __restrict__ W5, int phase)
{
    const int i = blockIdx.x * 256 + threadIdx.x;
    const float* src; __nv_bfloat16 *Dh, *Dl; int off;
    if (phase == 0) {
        if (i < 524288) { src = x;   Dh = g_xh;   Dl = g_xl;   off = i; }
        else            { src = rel; Dh = g_relh; Dl = g_rell; off = i - 524288; }
    } else {
        const int w = (phase == 1 ? 0 : 3) + (i >> 18);
        off = i & 262143;
        switch (w) {
            case 0:  src = W0; break; case 1: src = W1; break;
            case 2:  src = W2; break; case 3: src = W3; break;
            case 4:  src = W4; break; default: src = W5; break;
        }
        Dh = g_Wh[w]; Dl = g_Wl[w];
    }
    float4 v = ((const float4*)src)[off];
    __nv_bfloat16 h[4], l[4];
    split1(v.x, h[0], l[0]); split1(v.y, h[1], l[1]);
    split1(v.z, h[2], l[2]); split1(v.w, h[3], l[3]);
    *(uint2*)(Dh + off * 4) = *(uint2*)h;
    *(uint2*)(Dl + off * 4) = *(uint2*)l;
}

// ---------------------------------------------------------------------------
// HMMA GEMM core, 3-stage cp.async, 64B-pitch XOR-swizzled tiles.
// Tile row = 32 bf16 (64B) in 4 16B groups; phys_group = g ^ ((r>>1)&3).
// bf16x3: acc += Ah*Bh + Ah*Bl + Al*Bh, fp32 accumulation.
// ---------------------------------------------------------------------------
template<int NT>
__device__ __forceinline__ void gemm_core(
    const __nv_bfloat16* __restrict__ Ah, const __nv_bfloat16* __restrict__ Al, int lda,
    const __nv_bfloat16* __restrict__ Bh, const __nv_bfloat16* __restrict__ Bl, int ldb,
    int ktiles, float acc[2][NT][4])
{
    extern __shared__ __align__(16) __nv_bfloat16 dyn[];
    constexpr int ABYTES = 128 * 64;            // 8192
    constexpr int BBYTES = NT * 16 * 64;
    constexpr int STGB   = 2 * ABYTES + 2 * BBYTES;

    const int tid  = threadIdx.x;
    const int lane = tid & 31;
    const int wid  = tid >> 5;
    const int wm   = wid & 3;
    const int wn   = wid >> 2;
    const unsigned uB = smem_u32(dyn);

    const int arow0 = wm * 32 + (lane & 15);
    const int brow0 = wn * (NT * 8) + (lane & 7) + ((lane >> 4) << 3);
    const int aglog = lane >> 4;          // 0/1: which 16B half of the 32B ks-block
    const int bglog = (lane >> 3) & 1;

    auto issue = [&](int st, int kt) {
        const int kb = kt * 32;
        const unsigned sbase = uB + st * STGB;
#pragma unroll
        for (int s = 0; s < 2; s++) {                 // A: 512 16B chunks
            int ch = s * 256 + tid;
            int r = ch >> 2, g = ch & 3;
            unsigned o = (unsigned)(r * 64 + ((g ^ ((r >> 1) & 3)) << 4));
            cp16(sbase + o, Ah + r * lda + kb + g * 8);
            cp16(sbase + ABYTES + o, Al + r * lda + kb + g * 8);
        }
#pragma unroll
        for (int s = 0; s < NT / 4; s++) {            // B: NT*64 chunks
            int ch = s * 256 + tid;
            int r = ch >> 2, g = ch & 3;
            unsigned o = (unsigned)(r * 64 + ((g ^ ((r >> 1) & 3)) << 4));
            cp16(sbase + 2 * ABYTES + o, Bh + r * ldb + kb + g * 8);
            cp16(sbase + 2 * ABYTES + BBYTES + o, Bl + r * ldb + kb + g * 8);
        }
        CP_COMMIT();
    };

    issue(0, 0);
    if (ktiles > 1) issue(1, 1);

    for (int kt = 0; kt < ktiles; kt++) {
        const int st = kt % 3;
        if (kt + 2 < ktiles) { issue((kt + 2) % 3, kt + 2); CP_WAIT2(); }
        else if (kt + 1 < ktiles) { CP_WAIT1(); }
        else { CP_WAIT0(); }
        __syncthreads();

        const unsigned sbase = uB + st * STGB;
        const unsigned uAh = sbase, uAl = sbase + ABYTES;
        const unsigned uBh = sbase + 2 * ABYTES, uBl = uBh + BBYTES;

#pragma unroll
        for (int ks = 0; ks < 2; ks++) {
            unsigned ah[2][4], al[2][4];
#pragma unroll
            for (int mt = 0; mt < 2; mt++) {
                const int r = arow0 + mt * 16;
                const unsigned o = (unsigned)(r * 64 +
                    (((ks * 2 + aglog) ^ ((r >> 1) & 3)) << 4));
                ldsm4(ah[mt], uAh + o);
                ldsm4(al[mt], uAl + o);
            }
#pragma unroll
            for (int np = 0; np < NT / 2; np++) {
                const int r = brow0 + np * 16;
                const unsigned o = (unsigned)(r * 64 +
                    (((ks * 2 + bglog) ^ ((r >> 1) & 3)) << 4));
                unsigned bh[4], bl[4];
                ldsm4(bh, uBh + o);
                ldsm4(bl, uBl + o);
#pragma unroll
                for (int mt = 0; mt < 2; mt++) {
#pragma unroll
                    for (int sub = 0; sub < 2; sub++) {
                        float* c = acc[mt][np * 2 + sub];
                        mma_bf16(c, ah[mt], bh[sub * 2], bh[sub * 2 + 1]);
                        mma_bf16(c, ah[mt], bl[sub * 2], bl[sub * 2 + 1]);
                        mma_bf16(c, al[mt], bh[sub * 2], bh[sub * 2 + 1]);
                    }
                }
            }
        }
        __syncthreads();
    }
}

#define SMEM_NT8 (3 * (2 * 128 * 64 + 2 * 8 * 16 * 64))   // 98304
#define SMEM_NT4 (3 * (2 * 128 * 64 + 2 * 4 * 16 * 64))   // 73728

// ---------------------------------------------------------------------------
// Kernel 1: projections. z: 0=Q 1=K 2=V 3=QR 4=KR.  out head-major hi/lo bf16.
// ---------------------------------------------------------------------------
__global__ __launch_bounds__(256) void proj_mma(
    const float* __restrict__ bq, const float* __restrict__ bk,
    const float* __restrict__ bv, const float* __restrict__ bqr,
    const float* __restrict__ bkr)
{
    const int z = blockIdx.z;
    const __nv_bfloat16 *Ah, *Al;
    if (z < 3) { Ah = g_xh; Al = g_xl; } else { Ah = g_relh; Al = g_rell; }
    const __nv_bfloat16* Bh = g_Wh[z];
    const __nv_bfloat16* Bl = g_Wl[z];

    __nv_bfloat16 *Dh, *Dl; const float* bias;
    switch (z) {
        case 0:  Dh = g_qh;  Dl = g_ql;  bias = bq;  break;
        case 1:  Dh = g_kh;  Dl = g_kl;  bias = bk;  break;
        case 2:  Dh = g_vTh; Dl = g_vTl; bias = bv;  break;
        case 3:  Dh = g_qrh; Dl = g_qrl; bias = bqr; break;
        default: Dh = g_krh; Dl = g_krl; bias = bkr; break;
    }

    const int brow = blockIdx.y * 128;
    const int bcol = blockIdx.x * 128;

    float acc[2][8][4] = {};
    gemm_core<8>(Ah + brow * D_, Al + brow * D_, D_,
                 Bh + bcol * D_, Bl + bcol * D_, D_, 32, acc);

    const int lane = threadIdx.x & 31, wid = threadIdx.x >> 5;
    const int wm = wid & 3, wn = wid >> 2;
    const bool vtrans = (z == 2);

#pragma unroll
    for (int mt = 0; mt < 2; mt++) {
#pragma unroll
        for (int nt = 0; nt < 8; nt++) {
            const int n = bcol + wn * 64 + nt * 8 + (lane & 3) * 2;
            const int h = n >> 6, d = n & 63;
            const float b0 = __ldg(&bias[n]), b1 = __ldg(&bias[n + 1]);
#pragma unroll
            for (int half = 0; half < 2; half++) {
                const int m = brow + wm * 32 + mt * 16 + (lane >> 2) + half * 8;
                const int bb = m >> 10, s = m & (S_ - 1);
                float v0 = acc[mt][nt][half * 2 + 0] + b0;
                float v1 = acc[mt][nt][half * 2 + 1] + b1;
                __nv_bfloat16 h0, l0, h1, l1;
                split1(v0, h0, l0); split1(v1, h1, l1);
                if (!vtrans) {
                    const int idx = ((bb * H_ + h) * S_ + s) * DH_ + d;
                    __nv_bfloat162 ph; ph.x = h0; ph.y = h1;
                    __nv_bfloat162 pl; pl.x = l0; pl.y = l1;
                    *(__nv_bfloat162*)(Dh + idx) = ph;
                    *(__nv_bfloat162*)(Dl + idx) = pl;
                } else {
                    const int idx = ((bb * H_ + h) * DH_ + d) * S_ + s;
                    Dh[idx] = h0; Dh[idx + S_] = h1;
                    Dl[idx] = l0; Dl[idx + S_] = l1;
                }
            }
        }
    }
}

// ---------------------------------------------------------------------------
// Kernel 2: score GEMMs. z = bh*3 + which.  K = 64.
// which==0 (c2c): fp32 out.  which==1/2 (c2p/p2c): single-bf16 out.
// ---------------------------------------------------------------------------
__global__ __launch_bounds__(256) void scores_mma()
{
    const int z = blockIdx.z;
    const int bh = z / 3;
    const int which = z - bh * 3;
    const int ho = bh * S_ * DH_;

    const __nv_bfloat16 *Ah, *Al, *Bh, *Bl;
    float* Oc = nullptr; __nv_bfloat16* Ob = nullptr;
    if (which == 0)      { Ah = g_qh + ho;  Al = g_ql + ho;  Bh = g_kh + ho;  Bl = g_kl + ho;  Oc = g_c2c + bh * SS_; }
    else if (which == 1) { Ah = g_qh + ho;  Al = g_ql + ho;  Bh = g_krh + ho; Bl = g_krl + ho; Ob = g_c2pb + bh * SS_; }
    else                 { Ah = g_qrh + ho; Al = g_qrl + ho; Bh = g_kh + ho;  Bl = g_kl + ho;  Ob = g_p2cb + bh * SS_; }

    const int brow = blockIdx.y * 128;
    const int bcol = blockIdx.x * 128;

    float acc[2][8][4] = {};
    gemm_core<8>(Ah + brow * DH_, Al + brow * DH_, DH_,
                 Bh + bcol * DH_, Bl + bcol * DH_, DH_, 2, acc);

    const int lane = threadIdx.x & 31, wid = threadIdx.x >> 5;
    const int wm = wid & 3, wn = wid >> 2;
#pragma unroll
    for (int mt = 0; mt < 2; mt++) {
#pragma unroll
        for (int nt = 0; nt < 8; nt++) {
            const int n = bcol + wn * 64 + nt * 8 + (lane & 3) * 2;
#pragma unroll
            for (int half = 0; half < 2; half++) {
                const int m = brow + wm * 32 + mt * 16 + (lane >> 2) + half * 8;
                const float v0 = acc[mt][nt][half * 2];
                const float v1 = acc[mt][nt][half * 2 + 1];
                if (which == 0) {
                    *(float2*)(Oc + m * S_ + n) = make_float2(v0, v1);
                } else {
                    __nv_bfloat162 p;
                    p.x = __float2bfloat16(v0);
                    p.y = __float2bfloat16(v1);
                    *(__nv_bfloat162*)(Ob + m * S_ + n) = p;
                }
            }
        }
    }
}

// ---------------------------------------------------------------------------
// Combine: 32 x 128 tile, exact-window band staging from bf16 sources,
// float4 main loop.
// scores = (c2c + c2p[i, p(i,j)] + p2c[p(i,j), j]) / scale, + mask
// p(i,j) = clamp(i - j + 512, 0, 1023).
// c2pS[il][w]: w = 127 - jl  -> c2p[i0+il][clamp(P0+il-127+w)]
// p2cS[t][il]: t = il - jl + 127 -> p2c[clamp(P0-127+t)][j0 + il + 127 - t]
// ---------------------------------------------------------------------------
__global__ __launch_bounds__(256) void combine_kernel(const int* __restrict__ mask)
{
    const int bh = blockIdx.z;
    const int b  = bh >> 4;
    const int i0 = blockIdx.y * 32;
    const int j0 = blockIdx.x * 128;
    const int off = bh * SS_;
    const int P0 = i0 - j0 + 512;

    __shared__ float c2pS[32][132];   // pitch 132
    __shared__ float p2cS[159][33];   // pitch 33

    const int tid = threadIdx.x;

    // Stage c2p: row il needs p in [P0+il-127, P0+il]; scalar bf16, coalesced.
    {
        const int row0 = tid >> 5;          // 0..7
        const int w0   = (tid & 31) * 4;    // 0..124 step 4
#pragma unroll
        for (int rr = 0; rr < 4; rr++) {
            const int row = row0 + rr * 8;
            const __nv_bfloat16* src = g_c2pb + off + (i0 + row) * S_;
            const int pb = P0 + row - 127 + w0;
            float4 v;
            v.x = __bfloat162float(src[min(max(pb + 0, 0), S_ - 1)]);
            v.y = __bfloat162float(src[min(max(pb + 1, 0), S_ - 1)]);
            v.z = __bfloat162float(src[min(max(pb + 2, 0), S_ - 1)]);
            v.w = __bfloat162float(src[min(max(pb + 3, 0), S_ - 1)]);
            *(float4*)&c2pS[row][w0] = v;
        }
    }

    // Stage p2c: 159 t-rows x 32 slots, coalesced 32-wide per t-row (bf16).
#pragma unroll
    for (int it = 0; it < 20; it++) {
        const int seg = it * 256 + tid;
        if (seg < 159 * 32) {
            const int t  = seg >> 5;
            const int il = seg & 31;
            const int p  = min(max(P0 - 127 + t, 0), S_ - 1);
            const int j  = min(max(j0 + il + 127 - t, 0), S_ - 1);
            p2cS[t][il] = __bfloat162float(g_p2cb[off + p * S_ + j]);
        }
    }
    __syncthreads();

    const float invScale = 0.07216878364870323f;  // 1/sqrt(3*64)
    const int il = tid >> 3;
    const int jc = (tid & 7) * 4;
    float* crow = g_c2c + off + (i0 + il) * S_ + j0;
    const int* mrow = mask + b * S_ + j0;

#pragma unroll
    for (int pass = 0; pass < 4; pass++) {
        const int jl = jc + pass * 32;
        float4 c  = *(const float4*)(crow + jl);
        float4 cp = *(const float4*)&c2pS[il][124 - jl];   // reversed order
        const int tb = il - jl + 127;
        const float q0 = p2cS[tb    ][il];
        const float q1 = p2cS[tb - 1][il];
        const float q2 = p2cS[tb - 2][il];
        const float q3 = p2cS[tb - 3][il];
        const int4 mk = *(const int4*)(mrow + jl);

        float4 r;
        r.x = mk.x ? NEG_INF : (c.x + cp.w + q0) * invScale;
        r.y = mk.y ? NEG_INF : (c.y + cp.z + q1) * invScale;
        r.z = mk.z ? NEG_INF : (c.z + cp.y + q2) * invScale;
        r.w = mk.w ? NEG_INF : (c.w + cp.x + q3) * invScale;
        *(float4*)(crow + jl) = r;
    }
}

// ---------------------------------------------------------------------------
// Softmax: read fp32 scores, write probs as hi/lo bf16.
// ---------------------------------------------------------------------------
__global__ __launch_bounds__(256) void softmax_kernel()
{
    const int rowoff = blockIdx.y * SS_ + blockIdx.x * S_;
    const float* p = g_c2c + rowoff;
    const int tid = threadIdx.x;

    float4 v = *(const float4*)(p + tid * 4);
    float mx = fmaxf(fmaxf(v.x, v.y), fmaxf(v.z, v.w));
#pragma unroll
    for (int o = 16; o > 0; o >>= 1)
        mx = fmaxf(mx, __shfl_xor_sync(0xffffffffu, mx, o));

    __shared__ float smax[8], ssum[8];
    if ((tid & 31) == 0) smax[tid >> 5] = mx;
    __syncthreads();
    mx = fmaxf(fmaxf(fmaxf(smax[0], smax[1]), fmaxf(smax[2], smax[3])),
               fmaxf(fmaxf(smax[4], smax[5]), fmaxf(smax[6], smax[7])));

    v.x = __expf(v.x - mx);
    v.y = __expf(v.y - mx);
    v.z = __expf(v.z - mx);
    v.w = __expf(v.w - mx);
    float s = v.x + v.y + v.z + v.w;
#pragma unroll
    for (int o = 16; o > 0; o >>= 1)
        s += __shfl_xor_sync(0xffffffffu, s, o);
    if ((tid & 31) == 0) ssum[tid >> 5] = s;
    __syncthreads();
    s = ssum[0] + ssum[1] + ssum[2] + ssum[3] +
        ssum[4] + ssum[5] + ssum[6] + ssum[7];

    const float inv = 1.0f / s;
    v.x *= inv; v.y *= inv; v.z *= inv; v.w *= inv;

    __nv_bfloat16 h[4], l[4];
    split1(v.x, h[0], l[0]); split1(v.y, h[1], l[1]);
    split1(v.z, h[2], l[2]); split1(v.w, h[3], l[3]);
    *(uint2*)(g_ph + rowoff + tid * 4) = *(uint2*)h;
    *(uint2*)(g_pl + rowoff + tid * 4) = *(uint2*)l;
}

// ---------------------------------------------------------------------------
// Kernel 3: attn @ V  (probs 1024x1024 @ V 1024x64 per bh) -> ctx hi/lo bf16
// ---------------------------------------------------------------------------
__global__ __launch_bounds__(256) void av_mma()
{
    const int bh = blockIdx.y;
    const int i0 = blockIdx.x * 128;
    const __nv_bfloat16* Ah = g_ph + bh * SS_ + i0 * S_;
    const __nv_bfloat16* Al = g_pl + bh * SS_ + i0 * S_;
    const __nv_bfloat16* Bh = g_vTh + bh * DH_ * S_;
    const __nv_bfloat16* Bl = g_vTl + bh * DH_ * S_;

    float acc[2][4][4] = {};
    gemm_core<4>(Ah, Al, S_, Bh, Bl, S_, 32, acc);

    const int lane = threadIdx.x & 31, wid = threadIdx.x >> 5;
    const int wm = wid & 3, wn = wid >> 2;
    const int b = bh >> 4, h = bh & 15;

#pragma unroll
    for (int mt = 0; mt < 2; mt++) {
#pragma unroll
        for (int nt = 0; nt < 4; nt++) {
            const int d = wn * 32 + nt * 8 + (lane & 3) * 2;
#pragma unroll
            for (int half = 0; half < 2; half++) {
                const int s = i0 + wm * 32 + mt * 16 + (lane >> 2) + half * 8;
                const int idx = (b * S_ + s) * D_ + h * DH_ + d;
                float v0 = acc[mt][nt][half * 2 + 0];
                float v1 = acc[mt][nt][half * 2 + 1];
                __nv_bfloat16 h0, l0, h1, l1;
                split1(v0, h0, l0); split1(v1, h1, l1);
                __nv_bfloat162 ph; ph.x = h0; ph.y = h1;
                __nv_bfloat162 pl; pl.x = l0; pl.y = l1;
                *(__nv_bfloat162*)(g_ctxh + idx) = ph;
                *(__nv_bfloat162*)(g_ctxl + idx) = pl;
            }
        }
    }
}

// ---------------------------------------------------------------------------
// Kernel 4: output projection out = ctx @ Wc^T + bc  (fp32 out)
// ---------------------------------------------------------------------------
__global__ __launch_bounds__(256) void final_mma(
    const float* __restrict__ bc, float* __restrict__ out)
{
    const int brow = blockIdx.y * 128;
    const int bcol = blockIdx.x * 128;

    float acc[2][8][4] = {};
    gemm_core<8>(g_ctxh + brow * D_, g_ctxl + brow * D_, D_,
                 g_Wh[5] + bcol * D_, g_Wl[5] + bcol * D_, D_, 32, acc);

    const int lane = threadIdx.x & 31, wid = threadIdx.x >> 5;
    const int wm = wid & 3, wn = wid >> 2;
#pragma unroll
    for (int mt = 0; mt < 2; mt++) {
#pragma unroll
        for (int nt = 0; nt < 8; nt++) {
            const int n = bcol + wn * 64 + nt * 8 + (lane & 3) * 2;
            const float b0 = __ldg(&bc[n]), b1 = __ldg(&bc[n + 1]);
#pragma unroll
            for (int half = 0; half < 2; half++) {
                const int m = brow + wm * 32 + mt * 16 + (lane >> 2) + half * 8;
                *(float2*)(out + m * D_ + n) =
                    make_float2(acc[mt][nt][half * 2] + b0,
                                acc[mt][nt][half * 2 + 1] + b1);
            }
        }
    }
}

// ---------------------------------------------------------------------------
// Launch
// ---------------------------------------------------------------------------
extern "C" void kernel_launch(void* const* d_in, const int* in_sizes, int n_in,
                              void* d_out, int out_size)
{
    const float* x    = (const float*)d_in[0];
    const float* rel  = (const float*)d_in[1];
    const int*   mask = (const int*)  d_in[2];
    const float* Wq   = (const float*)d_in[3];
    const float* bq   = (const float*)d_in[4];
    const float* Wk   = (const float*)d_in[5];
    const float* bk   = (const float*)d_in[6];
    const float* Wv   = (const float*)d_in[7];
    const float* bv   = (const float*)d_in[8];
    const float* Wqr  = (const float*)d_in[9];
    const float* bqr  = (const float*)d_in[10];
    const float* Wkr  = (const float*)d_in[11];
    const float* bkr  = (const float*)d_in[12];
    const float* Wc   = (const float*)d_in[13];
    const float* bc   = (const float*)d_in[14];
    float* out = (float*)d_out;

    static int attr_done = 0;
    if (!attr_done) {
        cudaFuncSetAttribute(proj_mma,   cudaFuncAttributeMaxDynamicSharedMemorySize, SMEM_NT8);
        cudaFuncSetAttribute(scores_mma, cudaFuncAttributeMaxDynamicSharedMemorySize, SMEM_NT8);
        cudaFuncSetAttribute(av_mma,     cudaFuncAttributeMaxDynamicSharedMemorySize, SMEM_NT4);
        cudaFuncSetAttribute(final_mma,  cudaFuncAttributeMaxDynamicSharedMemorySize, SMEM_NT8);
        attr_done = 1;
    }

    // 0. Split fp32 operands into hi/lo bf16 (3 launches; puts proj_mma in
    //    ncu's capture slot for GEMM-side profiling)
    convert_all<<<4096, 256>>>(x, rel, Wq, Wk, Wv, Wqr, Wkr, Wc, 0);
    convert_all<<<3072, 256>>>(x, rel, Wq, Wk, Wv, Wqr, Wkr, Wc, 1);
    convert_all<<<3072, 256>>>(x, rel, Wq, Wk, Wv, Wqr, Wkr, Wc, 2);

    // 1. Projections (HMMA bf16x3, z-fused)
    proj_mma<<<dim3(D_ / 128, ROWS_ / 128, 5), 256, SMEM_NT8>>>(bq, bk, bv, bqr, bkr);

    // 2. Score GEMMs (c2c fp32, c2p/p2c bf16)
    scores_mma<<<dim3(S_ / 128, S_ / 128, BH_ * 3), 256, SMEM_NT8>>>();

    // 3. Banded gather + sum + scale + mask (bf16 band inputs)
    combine_kernel<<<dim3(S_ / 128, S_ / 32, BH_), 256>>>(mask);

    // 4. Softmax -> probs hi/lo bf16
    softmax_kernel<<<dim3(S_, BH_), 256>>>();

    // 5. attn @ V -> ctx hi/lo bf16
    av_mma<<<dim3(S_ / 128, BH_), 256, SMEM_NT4>>>();

    // 6. Output projection
    final_mma<<<dim3(D_ / 128, ROWS_ / 128), 256, SMEM_NT8>>>(bc, out);
}

// round 16
// speedup vs baseline: 1.4758x; 1.4264x over previous
#include <cuda_runtime.h>
#include <cuda_bf16.h>

// Problem constants
#define B_    2
#define S_    1024
#define D_    1024
#define H_    16
#define DH_   64
#define BH_   (B_*H_)      // 32
#define ROWS_ (B_*S_)      // 2048
#define SS_   (S_*S_)      // 1048576

#define NEG_INF __int_as_float(0xff800000)

// ---------------------------------------------------------------------------
// Device-global scratch (allocation-free rule). bf16 operands split hi/lo.
// ---------------------------------------------------------------------------
__device__ __align__(16) __nv_bfloat16 g_xh [ROWS_*D_], g_xl [ROWS_*D_];
__device__ __align__(16) __nv_bfloat16 g_relh[ROWS_*D_], g_rell[ROWS_*D_];
__device__ __align__(16) __nv_bfloat16 g_Wh[6][D_*D_],  g_Wl[6][D_*D_]; // q,k,v,qr,kr,c

__device__ __align__(16) __nv_bfloat16 g_qh [BH_*S_*DH_], g_ql [BH_*S_*DH_];
__device__ __align__(16) __nv_bfloat16 g_kh [BH_*S_*DH_], g_kl [BH_*S_*DH_];
__device__ __align__(16) __nv_bfloat16 g_qrh[BH_*S_*DH_], g_qrl[BH_*S_*DH_];
__device__ __align__(16) __nv_bfloat16 g_krh[BH_*S_*DH_], g_krl[BH_*S_*DH_];
__device__ __align__(16) __nv_bfloat16 g_vTh[BH_*DH_*S_], g_vTl[BH_*DH_*S_]; // [bh][d][s]

__device__ __align__(16) float g_c2c[BH_*SS_];                 // c2c scores / combined
__device__ __align__(16) __nv_bfloat16 g_c2pb[BH_*SS_];        // c2p_att (bf16)
__device__ __align__(16) __nv_bfloat16 g_p2cb[BH_*SS_];        // p2c_att (bf16)

__device__ __align__(16) __nv_bfloat16 g_ph[BH_*SS_], g_pl[BH_*SS_];     // probs
__device__ __align__(16) __nv_bfloat16 g_ctxh[ROWS_*D_], g_ctxl[ROWS_*D_];

// ---------------------------------------------------------------------------
// Helpers
// ---------------------------------------------------------------------------
__device__ __forceinline__ unsigned smem_u32(const void* p) {
    unsigned a;
    asm("{ .reg .u64 t; cvta.to.shared.u64 t, %1; cvt.u32.u64 %0, t; }"
        : "=r"(a) : "l"(p));
    return a;
}

__device__ __forceinline__ void ldsm4(unsigned r[4], unsigned a) {
    asm volatile("ldmatrix.sync.aligned.m8n8.x4.shared.b16 {%0,%1,%2,%3}, [%4];"
        : "=r"(r[0]), "=r"(r[1]), "=r"(r[2]), "=r"(r[3]) : "r"(a));
}

__device__ __forceinline__ void mma_bf16(float c[4], const unsigned a[4],
                                         unsigned b0, unsigned b1) {
    asm volatile(
        "mma.sync.aligned.m16n8k16.row.col.f32.bf16.bf16.f32 "
        "{%0,%1,%2,%3}, {%4,%5,%6,%7}, {%8,%9}, {%0,%1,%2,%3};"
        : "+f"(c[0]), "+f"(c[1]), "+f"(c[2]), "+f"(c[3])
        : "r"(a[0]), "r"(a[1]), "r"(a[2]), "r"(a[3]), "r"(b0), "r"(b1));
}

__device__ __forceinline__ void split1(float a, __nv_bfloat16& h, __nv_bfloat16& l) {
    h = __float2bfloat16(a);
    l = __float2bfloat16(a - __bfloat162float(h));
}

__device__ __forceinline__ void cp16(unsigned s, const void* g) {
    asm volatile("cp.async.cg.shared.global [%0], [%1], 16;" :: "r"(s), "l"(g));
}
#define CP_COMMIT() asm volatile("cp.async.commit_group;" ::: "memory")
#define CP_WAIT0()  asm volatile("cp.async.wait_group 0;" ::: "memory")
#define CP_WAIT1()  asm volatile("cp.async.wait_group 1;" ::: "memory")

// ---------------------------------------------------------------------------
// Operand conversion: fp32 -> hi/lo bf16, all 8 tensors in one launch.
// ---------------------------------------------------------------------------
__global__ __launch_bounds__(256) void convert_all(
    const float* __restrict__ x,  const float* __restrict__ rel,
    const float* __restrict__ W0, const float* __restrict__ W1,
    const float* __restrict__ W2, const float* __restrict__ W3,
    const float* __restrict__ W4, const float* __restrict__ W5)
{
    const int i = blockIdx.x * 256 + threadIdx.x;   // grid covers 2621440
    const float* src; __nv_bfloat16 *Dh, *Dl; int off;
    if (i < 1048576) {
        if (i < 524288) { src = x;   Dh = g_xh;   Dl = g_xl;   off = i; }
        else            { src = rel; Dh = g_relh; Dl = g_rell; off = i - 524288; }
    } else {
        const int w = (i - 1048576) >> 18;
        off = (i - 1048576) & 262143;
        switch (w) {
            case 0:  src = W0; break; case 1: src = W1; break;
            case 2:  src = W2; break; case 3: src = W3; break;
            case 4:  src = W4; break; default: src = W5; break;
        }
        Dh = g_Wh[w]; Dl = g_Wl[w];
    }
    float4 v = ((const float4*)src)[off];
    __nv_bfloat16 h[4], l[4];
    split1(v.x, h[0], l[0]); split1(v.y, h[1], l[1]);
    split1(v.z, h[2], l[2]); split1(v.w, h[3], l[3]);
    *(uint2*)(Dh + off * 4) = *(uint2*)h;
    *(uint2*)(Dl + off * 4) = *(uint2*)l;
}

// ---------------------------------------------------------------------------
// HMMA GEMM core, cp.async double-buffered (R10-proven layout: 80B pitch).
// PASSES=3: Ah*Bh + Ah*Bl + Al*Bh.  PASSES=2: Ah*Bh + Ah*Bl (Al not staged).
// ---------------------------------------------------------------------------
template<int NT, int PASSES>
__device__ __forceinline__ void gemm_core(
    const __nv_bfloat16* __restrict__ Ah, const __nv_bfloat16* __restrict__ Al, int lda,
    const __nv_bfloat16* __restrict__ Bh, const __nv_bfloat16* __restrict__ Bl, int ldb,
    int ktiles, float acc[2][NT][4])
{
    extern __shared__ __align__(16) __nv_bfloat16 dyn[];
    constexpr int ABYTES = 128 * 40 * 2;        // 10240
    constexpr int BBYTES = NT * 16 * 40 * 2;
    constexpr int STGB   = 2 * ABYTES + 2 * BBYTES;

    const int tid  = threadIdx.x;
    const int lane = tid & 31;
    const int wid  = tid >> 5;
    const int wm   = wid & 3;
    const int wn   = wid >> 2;
    const unsigned uB = smem_u32(dyn);

    const unsigned aoff = (unsigned)((wm * 32 + (lane & 15)) * 80 + ((lane >> 4) << 4));
    const unsigned boff = (unsigned)((wn * (NT * 8) + (lane & 7) + ((lane >> 4) << 3)) * 80
                                     + (((lane >> 3) & 1) << 4));

    auto issue = [&](int st, int kt) {
        const int kb = kt * 32;
        const unsigned sbase = uB + st * STGB;
#pragma unroll
        for (int s = 0; s < 2; s++) {                 // A: 512 chunks
            int ch = s * 256 + tid;
            int r = ch >> 2, ks = ch & 3;
            unsigned o = (unsigned)(r * 80 + ks * 16);
            cp16(sbase + o, Ah + r * lda + kb + ks * 8);
            if (PASSES == 3)
                cp16(sbase + ABYTES + o, Al + r * lda + kb + ks * 8);
        }
#pragma unroll
        for (int s = 0; s < NT / 4; s++) {            // B: NT*64 chunks
            int ch = s * 256 + tid;
            int r = ch >> 2, ks = ch & 3;
            unsigned o = (unsigned)(r * 80 + ks * 16);
            cp16(sbase + 2 * ABYTES + o, Bh + r * ldb + kb + ks * 8);
            cp16(sbase + 2 * ABYTES + BBYTES + o, Bl + r * ldb + kb + ks * 8);
        }
        CP_COMMIT();
    };

    issue(0, 0);

    for (int kt = 0; kt < ktiles; kt++) {
        const int st = kt & 1;
        if (kt + 1 < ktiles) { issue(st ^ 1, kt + 1); CP_WAIT1(); }
        else                 { CP_WAIT0(); }
        __syncthreads();

        const unsigned sbase = uB + st * STGB;
        const unsigned uAh = sbase, uAl = sbase + ABYTES;
        const unsigned uBh = sbase + 2 * ABYTES, uBl = uBh + BBYTES;

#pragma unroll
        for (int ks = 0; ks < 2; ks++) {
            unsigned ah[2][4], al[2][4];
#pragma unroll
            for (int mt = 0; mt < 2; mt++) {
                unsigned o = aoff + mt * 16 * 80 + ks * 32;
                ldsm4(ah[mt], uAh + o);
                if (PASSES == 3) ldsm4(al[mt], uAl + o);
            }
#pragma unroll
            for (int np = 0; np < NT / 2; np++) {
                unsigned o = boff + np * 16 * 80 + ks * 32;
                unsigned bh[4], bl[4];
                ldsm4(bh, uBh + o);
                ldsm4(bl, uBl + o);
#pragma unroll
                for (int mt = 0; mt < 2; mt++) {
#pragma unroll
                    for (int sub = 0; sub < 2; sub++) {
                        float* c = acc[mt][np * 2 + sub];
                        mma_bf16(c, ah[mt], bh[sub * 2], bh[sub * 2 + 1]);
                        mma_bf16(c, ah[mt], bl[sub * 2], bl[sub * 2 + 1]);
                        if (PASSES == 3)
                            mma_bf16(c, al[mt], bh[sub * 2], bh[sub * 2 + 1]);
                    }
                }
            }
        }
        __syncthreads();
    }
}

#define SMEM_NT8 (2 * (2 * 128 * 40 * 2 + 2 * 8 * 16 * 40 * 2))   // 81920
#define SMEM_NT4 (2 * (2 * 128 * 40 * 2 + 2 * 4 * 16 * 40 * 2))   // 61440

// ---------------------------------------------------------------------------
// Kernel 1: projections. z: 0=Q 1=K 2=V 3=QR 4=KR.  out head-major hi/lo bf16.
// ---------------------------------------------------------------------------
__global__ __launch_bounds__(256) void proj_mma(
    const float* __restrict__ bq, const float* __restrict__ bk,
    const float* __restrict__ bv, const float* __restrict__ bqr,
    const float* __restrict__ bkr)
{
    const int z = blockIdx.z;
    const __nv_bfloat16 *Ah, *Al;
    if (z < 3) { Ah = g_xh; Al = g_xl; } else { Ah = g_relh; Al = g_rell; }
    const __nv_bfloat16* Bh = g_Wh[z];
    const __nv_bfloat16* Bl = g_Wl[z];

    __nv_bfloat16 *Dh, *Dl; const float* bias;
    switch (z) {
        case 0:  Dh = g_qh;  Dl = g_ql;  bias = bq;  break;
        case 1:  Dh = g_kh;  Dl = g_kl;  bias = bk;  break;
        case 2:  Dh = g_vTh; Dl = g_vTl; bias = bv;  break;
        case 3:  Dh = g_qrh; Dl = g_qrl; bias = bqr; break;
        default: Dh = g_krh; Dl = g_krl; bias = bkr; break;
    }

    const int brow = blockIdx.y * 128;
    const int bcol = blockIdx.x * 128;

    float acc[2][8][4] = {};
    gemm_core<8, 3>(Ah + brow * D_, Al + brow * D_, D_,
                    Bh + bcol * D_, Bl + bcol * D_, D_, 32, acc);

    const int lane = threadIdx.x & 31, wid = threadIdx.x >> 5;
    const int wm = wid & 3, wn = wid >> 2;
    const bool vtrans = (z == 2);

#pragma unroll
    for (int mt = 0; mt < 2; mt++) {
#pragma unroll
        for (int nt = 0; nt < 8; nt++) {
            const int n = bcol + wn * 64 + nt * 8 + (lane & 3) * 2;
            const int h = n >> 6, d = n & 63;
            const float b0 = __ldg(&bias[n]), b1 = __ldg(&bias[n + 1]);
#pragma unroll
            for (int half = 0; half < 2; half++) {
                const int m = brow + wm * 32 + mt * 16 + (lane >> 2) + half * 8;
                const int bb = m >> 10, s = m & (S_ - 1);
                float v0 = acc[mt][nt][half * 2 + 0] + b0;
                float v1 = acc[mt][nt][half * 2 + 1] + b1;
                __nv_bfloat16 h0, l0, h1, l1;
                split1(v0, h0, l0); split1(v1, h1, l1);
                if (!vtrans) {
                    const int idx = ((bb * H_ + h) * S_ + s) * DH_ + d;
                    __nv_bfloat162 ph; ph.x = h0; ph.y = h1;
                    __nv_bfloat162 pl; pl.x = l0; pl.y = l1;
                    *(__nv_bfloat162*)(Dh + idx) = ph;
                    *(__nv_bfloat162*)(Dl + idx) = pl;
                } else {
                    const int idx = ((bb * H_ + h) * DH_ + d) * S_ + s;
                    Dh[idx] = h0; Dh[idx + S_] = h1;
                    Dl[idx] = l0; Dl[idx + S_] = l1;
                }
            }
        }
    }
}

// ---------------------------------------------------------------------------
// Kernel 2: score GEMMs, 2-pass. z = bh*3 + which.  K = 64.
// which==0 (c2c): fp32 out.  which==1/2 (c2p/p2c): single-bf16 out.
// ---------------------------------------------------------------------------
__global__ __launch_bounds__(256) void scores_mma()
{
    const int z = blockIdx.z;
    const int bh = z / 3;
    const int which = z - bh * 3;
    const int ho = bh * S_ * DH_;

    const __nv_bfloat16 *Ah, *Al, *Bh, *Bl;
    float* Oc = nullptr; __nv_bfloat16* Ob = nullptr;
    if (which == 0)      { Ah = g_qh + ho;  Al = g_ql + ho;  Bh = g_kh + ho;  Bl = g_kl + ho;  Oc = g_c2c + bh * SS_; }
    else if (which == 1) { Ah = g_qh + ho;  Al = g_ql + ho;  Bh = g_krh + ho; Bl = g_krl + ho; Ob = g_c2pb + bh * SS_; }
    else                 { Ah = g_qrh + ho; Al = g_qrl + ho; Bh = g_kh + ho;  Bl = g_kl + ho;  Ob = g_p2cb + bh * SS_; }

    const int brow = blockIdx.y * 128;
    const int bcol = blockIdx.x * 128;

    float acc[2][8][4] = {};
    gemm_core<8, 2>(Ah + brow * DH_, Al + brow * DH_, DH_,
                    Bh + bcol * DH_, Bl + bcol * DH_, DH_, 2, acc);

    const int lane = threadIdx.x & 31, wid = threadIdx.x >> 5;
    const int wm = wid & 3, wn = wid >> 2;
#pragma unroll
    for (int mt = 0; mt < 2; mt++) {
#pragma unroll
        for (int nt = 0; nt < 8; nt++) {
            const int n = bcol + wn * 64 + nt * 8 + (lane & 3) * 2;
#pragma unroll
            for (int half = 0; half < 2; half++) {
                const int m = brow + wm * 32 + mt * 16 + (lane >> 2) + half * 8;
                const float v0 = acc[mt][nt][half * 2];
                const float v1 = acc[mt][nt][half * 2 + 1];
                if (which == 0) {
                    *(float2*)(Oc + m * S_ + n) = make_float2(v0, v1);
                } else {
                    __nv_bfloat162 p;
                    p.x = __float2bfloat16(v0);
                    p.y = __float2bfloat16(v1);
                    *(__nv_bfloat162*)(Ob + m * S_ + n) = p;
                }
            }
        }
    }
}

// ---------------------------------------------------------------------------
// Combine: 32 x 128 tile, exact-window band staging from bf16 sources,
// float4 main loop.
// scores = (c2c + c2p[i, p(i,j)] + p2c[p(i,j), j]) / scale, + mask
// p(i,j) = clamp(i - j + 512, 0, 1023).
// c2pS[il][w]: w = 127 - jl  -> c2p[i0+il][clamp(P0+il-127+w)]
// p2cS[t][il]: t = il - jl + 127 -> p2c[clamp(P0-127+t)][j0 + il + 127 - t]
// ---------------------------------------------------------------------------
__global__ __launch_bounds__(256) void combine_kernel(const int* __restrict__ mask)
{
    const int bh = blockIdx.z;
    const int b  = bh >> 4;
    const int i0 = blockIdx.y * 32;
    const int j0 = blockIdx.x * 128;
    const int off = bh * SS_;
    const int P0 = i0 - j0 + 512;

    __shared__ float c2pS[32][132];   // pitch 132
    __shared__ float p2cS[159][33];   // pitch 33

    const int tid = threadIdx.x;

    // Stage c2p: row il needs p in [P0+il-127, P0+il]; scalar bf16, coalesced.
    {
        const int row0 = tid >> 5;          // 0..7
        const int w0   = (tid & 31) * 4;    // 0..124 step 4
#pragma unroll
        for (int rr = 0; rr < 4; rr++) {
            const int row = row0 + rr * 8;
            const __nv_bfloat16* src = g_c2pb + off + (i0 + row) * S_;
            const int pb = P0 + row - 127 + w0;
            float4 v;
            v.x = __bfloat162float(src[min(max(pb + 0, 0), S_ - 1)]);
            v.y = __bfloat162float(src[min(max(pb + 1, 0), S_ - 1)]);
            v.z = __bfloat162float(src[min(max(pb + 2, 0), S_ - 1)]);
            v.w = __bfloat162float(src[min(max(pb + 3, 0), S_ - 1)]);
            *(float4*)&c2pS[row][w0] = v;
        }
    }

    // Stage p2c: 159 t-rows x 32 slots, coalesced 32-wide per t-row (bf16).
#pragma unroll
    for (int it = 0; it < 20; it++) {
        const int seg = it * 256 + tid;
        if (seg < 159 * 32) {
            const int t  = seg >> 5;
            const int il = seg & 31;
            const int p  = min(max(P0 - 127 + t, 0), S_ - 1);
            const int j  = min(max(j0 + il + 127 - t, 0), S_ - 1);
            p2cS[t][il] = __bfloat162float(g_p2cb[off + p * S_ + j]);
        }
    }
    __syncthreads();

    const float invScale = 0.07216878364870323f;  // 1/sqrt(3*64)
    const int il = tid >> 3;
    const int jc = (tid & 7) * 4;
    float* crow = g_c2c + off + (i0 + il) * S_ + j0;
    const int* mrow = mask + b * S_ + j0;

#pragma unroll
    for (int pass = 0; pass < 4; pass++) {
        const int jl = jc + pass * 32;
        float4 c  = *(const float4*)(crow + jl);
        float4 cp = *(const float4*)&c2pS[il][124 - jl];   // reversed order
        const int tb = il - jl + 127;
        const float q0 = p2cS[tb    ][il];
        const float q1 = p2cS[tb - 1][il];
        const float q2 = p2cS[tb - 2][il];
        const float q3 = p2cS[tb - 3][il];
        const int4 mk = *(const int4*)(mrow + jl);

        float4 r;
        r.x = mk.x ? NEG_INF : (c.x + cp.w + q0) * invScale;
        r.y = mk.y ? NEG_INF : (c.y + cp.z + q1) * invScale;
        r.z = mk.z ? NEG_INF : (c.z + cp.y + q2) * invScale;
        r.w = mk.w ? NEG_INF : (c.w + cp.x + q3) * invScale;
        *(float4*)(crow + jl) = r;
    }
}

// ---------------------------------------------------------------------------
// Softmax: read fp32 scores, write probs as hi/lo bf16.
// ---------------------------------------------------------------------------
__global__ __launch_bounds__(256) void softmax_kernel()
{
    const int rowoff = blockIdx.y * SS_ + blockIdx.x * S_;
    const float* p = g_c2c + rowoff;
    const int tid = threadIdx.x;

    float4 v = *(const float4*)(p + tid * 4);
    float mx = fmaxf(fmaxf(v.x, v.y), fmaxf(v.z, v.w));
#pragma unroll
    for (int o = 16; o > 0; o >>= 1)
        mx = fmaxf(mx, __shfl_xor_sync(0xffffffffu, mx, o));

    __shared__ float smax[8], ssum[8];
    if ((tid & 31) == 0) smax[tid >> 5] = mx;
    __syncthreads();
    mx = fmaxf(fmaxf(fmaxf(smax[0], smax[1]), fmaxf(smax[2], smax[3])),
               fmaxf(fmaxf(smax[4], smax[5]), fmaxf(smax[6], smax[7])));

    v.x = __expf(v.x - mx);
    v.y = __expf(v.y - mx);
    v.z = __expf(v.z - mx);
    v.w = __expf(v.w - mx);
    float s = v.x + v.y + v.z + v.w;
#pragma unroll
    for (int o = 16; o > 0; o >>= 1)
        s += __shfl_xor_sync(0xffffffffu, s, o);
    if ((tid & 31) == 0) ssum[tid >> 5] = s;
    __syncthreads();
    s = ssum[0] + ssum[1] + ssum[2] + ssum[3] +
        ssum[4] + ssum[5] + ssum[6] + ssum[7];

    const float inv = 1.0f / s;
    v.x *= inv; v.y *= inv; v.z *= inv; v.w *= inv;

    __nv_bfloat16 h[4], l[4];
    split1(v.x, h[0], l[0]); split1(v.y, h[1], l[1]);
    split1(v.z, h[2], l[2]); split1(v.w, h[3], l[3]);
    *(uint2*)(g_ph + rowoff + tid * 4) = *(uint2*)h;
    *(uint2*)(g_pl + rowoff + tid * 4) = *(uint2*)l;
}

// ---------------------------------------------------------------------------
// Kernel 3: attn @ V  (probs 1024x1024 @ V 1024x64 per bh) -> ctx hi/lo bf16
// ---------------------------------------------------------------------------
__global__ __launch_bounds__(256) void av_mma()
{
    const int bh = blockIdx.y;
    const int i0 = blockIdx.x * 128;
    const __nv_bfloat16* Ah = g_ph + bh * SS_ + i0 * S_;
    const __nv_bfloat16* Al = g_pl + bh * SS_ + i0 * S_;
    const __nv_bfloat16* Bh = g_vTh + bh * DH_ * S_;
    const __nv_bfloat16* Bl = g_vTl + bh * DH_ * S_;

    float acc[2][4][4] = {};
    gemm_core<4, 3>(Ah, Al, S_, Bh, Bl, S_, 32, acc);

    const int lane = threadIdx.x & 31, wid = threadIdx.x >> 5;
    const int wm = wid & 3, wn = wid >> 2;
    const int b = bh >> 4, h = bh & 15;

#pragma unroll
    for (int mt = 0; mt < 2; mt++) {
#pragma unroll
        for (int nt = 0; nt < 4; nt++) {
            const int d = wn * 32 + nt * 8 + (lane & 3) * 2;
#pragma unroll
            for (int half = 0; half < 2; half++) {
                const int s = i0 + wm * 32 + mt * 16 + (lane >> 2) + half * 8;
                const int idx = (b * S_ + s) * D_ + h * DH_ + d;
                float v0 = acc[mt][nt][half * 2 + 0];
                float v1 = acc[mt][nt][half * 2 + 1];
                __nv_bfloat16 h0, l0, h1, l1;
                split1(v0, h0, l0); split1(v1, h1, l1);
                __nv_bfloat162 ph; ph.x = h0; ph.y = h1;
                __nv_bfloat162 pl; pl.x = l0; pl.y = l1;
                *(__nv_bfloat162*)(g_ctxh + idx) = ph;
                *(__nv_bfloat162*)(g_ctxl + idx) = pl;
            }
        }
    }
}

// ---------------------------------------------------------------------------
// Kernel 4: output projection out = ctx @ Wc^T + bc  (fp32 out)
// ---------------------------------------------------------------------------
__global__ __launch_bounds__(256) void final_mma(
    const float* __restrict__ bc, float* __restrict__ out)
{
    const int brow = blockIdx.y * 128;
    const int bcol = blockIdx.x * 128;

    float acc[2][8][4] = {};
    gemm_core<8, 3>(g_ctxh + brow * D_, g_ctxl + brow * D_, D_,
                    g_Wh[5] + bcol * D_, g_Wl[5] + bcol * D_, D_, 32, acc);

    const int lane = threadIdx.x & 31, wid = threadIdx.x >> 5;
    const int wm = wid & 3, wn = wid >> 2;
#pragma unroll
    for (int mt = 0; mt < 2; mt++) {
#pragma unroll
        for (int nt = 0; nt < 8; nt++) {
            const int n = bcol + wn * 64 + nt * 8 + (lane & 3) * 2;
            const float b0 = __ldg(&bc[n]), b1 = __ldg(&bc[n + 1]);
#pragma unroll
            for (int half = 0; half < 2; half++) {
                const int m = brow + wm * 32 + mt * 16 + (lane >> 2) + half * 8;
                *(float2*)(out + m * D_ + n) =
                    make_float2(acc[mt][nt][half * 2] + b0,
                                acc[mt][nt][half * 2 + 1] + b1);
            }
        }
    }
}

// ---------------------------------------------------------------------------
// Launch
// ---------------------------------------------------------------------------
extern "C" void kernel_launch(void* const* d_in, const int* in_sizes, int n_in,
                              void* d_out, int out_size)
{
    const float* x    = (const float*)d_in[0];
    const float* rel  = (const float*)d_in[1];
    const int*   mask = (const int*)  d_in[2];
    const float* Wq   = (const float*)d_in[3];
    const float* bq   = (const float*)d_in[4];
    const float* Wk   = (const float*)d_in[5];
    const float* bk   = (const float*)d_in[6];
    const float* Wv   = (const float*)d_in[7];
    const float* bv   = (const float*)d_in[8];
    const float* Wqr  = (const float*)d_in[9];
    const float* bqr  = (const float*)d_in[10];
    const float* Wkr  = (const float*)d_in[11];
    const float* bkr  = (const float*)d_in[12];
    const float* Wc   = (const float*)d_in[13];
    const float* bc   = (const float*)d_in[14];
    float* out = (float*)d_out;

    static int attr_done = 0;
    if (!attr_done) {
        cudaFuncSetAttribute(proj_mma,   cudaFuncAttributeMaxDynamicSharedMemorySize, SMEM_NT8);
        cudaFuncSetAttribute(scores_mma, cudaFuncAttributeMaxDynamicSharedMemorySize, SMEM_NT8);
        cudaFuncSetAttribute(av_mma,     cudaFuncAttributeMaxDynamicSharedMemorySize, SMEM_NT4);
        cudaFuncSetAttribute(final_mma,  cudaFuncAttributeMaxDynamicSharedMemorySize, SMEM_NT8);
        attr_done = 1;
    }

    // 0. Split fp32 operands into hi/lo bf16 (single launch)
    convert_all<<<2621440 / 256, 256>>>(x, rel, Wq, Wk, Wv, Wqr, Wkr, Wc);

    // 1. Projections (HMMA bf16x3, z-fused)
    proj_mma<<<dim3(D_ / 128, ROWS_ / 128, 5), 256, SMEM_NT8>>>(bq, bk, bv, bqr, bkr);

    // 2. Score GEMMs (bf16x2 2-pass; c2c fp32, c2p/p2c bf16)
    scores_mma<<<dim3(S_ / 128, S_ / 128, BH_ * 3), 256, SMEM_NT8>>>();

    // 3. Banded gather + sum + scale + mask (bf16 band inputs)
    combine_kernel<<<dim3(S_ / 128, S_ / 32, BH_), 256>>>(mask);

    // 4. Softmax -> probs hi/lo bf16
    softmax_kernel<<<dim3(S_, BH_), 256>>>();

    // 5. attn @ V -> ctx hi/lo bf16 (bf16x3)
    av_mma<<<dim3(S_ / 128, BH_), 256, SMEM_NT4>>>();

    // 6. Output projection (bf16x3)
    final_mma<<<dim3(D_ / 128, ROWS_ / 128), 256, SMEM_NT8>>>(bc, out);
}

// round 17
// speedup vs baseline: 1.4875x; 1.0079x over previous
#include <cuda_runtime.h>
#include <cuda_bf16.h>

// Problem constants
#define B_    2
#define S_    1024
#define D_    1024
#define H_    16
#define DH_   64
#define BH_   (B_*H_)      // 32
#define ROWS_ (B_*S_)      // 2048
#define SS_   (S_*S_)      // 1048576

#define NEG_INF __int_as_float(0xff800000)

// ---------------------------------------------------------------------------
// Device-global scratch (allocation-free rule). bf16 operands split hi/lo.
// ---------------------------------------------------------------------------
__device__ __align__(16) __nv_bfloat16 g_xh [ROWS_*D_], g_xl [ROWS_*D_];
__device__ __align__(16) __nv_bfloat16 g_relh[ROWS_*D_], g_rell[ROWS_*D_];
__device__ __align__(16) __nv_bfloat16 g_Wh[6][D_*D_],  g_Wl[6][D_*D_]; // q,k,v,qr,kr,c

__device__ __align__(16) __nv_bfloat16 g_qh [BH_*S_*DH_], g_ql [BH_*S_*DH_];
__device__ __align__(16) __nv_bfloat16 g_kh [BH_*S_*DH_], g_kl [BH_*S_*DH_];
__device__ __align__(16) __nv_bfloat16 g_qrh[BH_*S_*DH_], g_qrl[BH_*S_*DH_];
__device__ __align__(16) __nv_bfloat16 g_krh[BH_*S_*DH_], g_krl[BH_*S_*DH_];
__device__ __align__(16) __nv_bfloat16 g_vTh[BH_*DH_*S_], g_vTl[BH_*DH_*S_]; // [bh][d][s]

__device__ __align__(16) float g_c2c[BH_*SS_];                 // c2c scores / combined
__device__ __align__(16) __nv_bfloat16 g_c2pb[BH_*SS_];        // c2p_att (bf16)
__device__ __align__(16) __nv_bfloat16 g_p2cb[BH_*SS_];        // p2c_att (bf16)

__device__ __align__(16) __nv_bfloat16 g_ph[BH_*SS_], g_pl[BH_*SS_];     // probs
__device__ __align__(16) __nv_bfloat16 g_ctxh[ROWS_*D_], g_ctxl[ROWS_*D_];

// ---------------------------------------------------------------------------
// Helpers
// ---------------------------------------------------------------------------
__device__ __forceinline__ unsigned smem_u32(const void* p) {
    unsigned a;
    asm("{ .reg .u64 t; cvta.to.shared.u64 t, %1; cvt.u32.u64 %0, t; }"
        : "=r"(a) : "l"(p));
    return a;
}

__device__ __forceinline__ void ldsm4(unsigned r[4], unsigned a) {
    asm volatile("ldmatrix.sync.aligned.m8n8.x4.shared.b16 {%0,%1,%2,%3}, [%4];"
        : "=r"(r[0]), "=r"(r[1]), "=r"(r[2]), "=r"(r[3]) : "r"(a));
}

__device__ __forceinline__ void mma_bf16(float c[4], const unsigned a[4],
                                         unsigned b0, unsigned b1) {
    asm volatile(
        "mma.sync.aligned.m16n8k16.row.col.f32.bf16.bf16.f32 "
        "{%0,%1,%2,%3}, {%4,%5,%6,%7}, {%8,%9}, {%0,%1,%2,%3};"
        : "+f"(c[0]), "+f"(c[1]), "+f"(c[2]), "+f"(c[3])
        : "r"(a[0]), "r"(a[1]), "r"(a[2]), "r"(a[3]), "r"(b0), "r"(b1));
}

__device__ __forceinline__ void split1(float a, __nv_bfloat16& h, __nv_bfloat16& l) {
    h = __float2bfloat16(a);
    l = __float2bfloat16(a - __bfloat162float(h));
}

__device__ __forceinline__ void cp16(unsigned s, const void* g) {
    asm volatile("cp.async.cg.shared.global [%0], [%1], 16;" :: "r"(s), "l"(g));
}
#define CP_COMMIT() asm volatile("cp.async.commit_group;" ::: "memory")
#define CP_WAIT0()  asm volatile("cp.async.wait_group 0;" ::: "memory")

// ---------------------------------------------------------------------------
// Operand conversion: fp32 -> hi/lo bf16, all 8 tensors in one launch.
// ---------------------------------------------------------------------------
__global__ __launch_bounds__(256) void convert_all(
    const float* __restrict__ x,  const float* __restrict__ rel,
    const float* __restrict__ W0, const float* __restrict__ W1,
    const float* __restrict__ W2, const float* __restrict__ W3,
    const float* __restrict__ W4, const float* __restrict__ W5)
{
    const int i = blockIdx.x * 256 + threadIdx.x;   // grid covers 2621440
    const float* src; __nv_bfloat16 *Dh, *Dl; int off;
    if (i < 1048576) {
        if (i < 524288) { src = x;   Dh = g_xh;   Dl = g_xl;   off = i; }
        else            { src = rel; Dh = g_relh; Dl = g_rell; off = i - 524288; }
    } else {
        const int w = (i - 1048576) >> 18;
        off = (i - 1048576) & 262143;
        switch (w) {
            case 0:  src = W0; break; case 1: src = W1; break;
            case 2:  src = W2; break; case 3: src = W3; break;
            case 4:  src = W4; break; default: src = W5; break;
        }
        Dh = g_Wh[w]; Dl = g_Wl[w];
    }
    float4 v = ((const float4*)src)[off];
    __nv_bfloat16 h[4], l[4];
    split1(v.x, h[0], l[0]); split1(v.y, h[1], l[1]);
    split1(v.z, h[2], l[2]); split1(v.w, h[3], l[3]);
    *(uint2*)(Dh + off * 4) = *(uint2*)h;
    *(uint2*)(Dl + off * 4) = *(uint2*)l;
}

// ---------------------------------------------------------------------------
// HMMA GEMM core, cp.async double-buffered, SINGLE sync per K-chunk.
// Loop: wait(data kt) -> sync (prev consumers done) -> issue(kt+1 into other
// stage, overlaps compute) -> compute(kt).
// PASSES=3: Ah*Bh + Ah*Bl + Al*Bh.  PASSES=2: Ah*Bh + Ah*Bl (Al not staged).
// ---------------------------------------------------------------------------
template<int NT, int PASSES>
__device__ __forceinline__ void gemm_core(
    const __nv_bfloat16* __restrict__ Ah, const __nv_bfloat16* __restrict__ Al, int lda,
    const __nv_bfloat16* __restrict__ Bh, const __nv_bfloat16* __restrict__ Bl, int ldb,
    int ktiles, float acc[2][NT][4])
{
    extern __shared__ __align__(16) __nv_bfloat16 dyn[];
    constexpr int ABYTES = 128 * 40 * 2;        // 10240
    constexpr int BBYTES = NT * 16 * 40 * 2;
    constexpr int STGB   = 2 * ABYTES + 2 * BBYTES;

    const int tid  = threadIdx.x;
    const int lane = tid & 31;
    const int wid  = tid >> 5;
    const int wm   = wid & 3;
    const int wn   = wid >> 2;
    const unsigned uB = smem_u32(dyn);

    const unsigned aoff = (unsigned)((wm * 32 + (lane & 15)) * 80 + ((lane >> 4) << 4));
    const unsigned boff = (unsigned)((wn * (NT * 8) + (lane & 7) + ((lane >> 4) << 3)) * 80
                                     + (((lane >> 3) & 1) << 4));

    auto issue = [&](int st, int kt) {
        const int kb = kt * 32;
        const unsigned sbase = uB + st * STGB;
#pragma unroll
        for (int s = 0; s < 2; s++) {                 // A: 512 chunks
            int ch = s * 256 + tid;
            int r = ch >> 2, ks = ch & 3;
            unsigned o = (unsigned)(r * 80 + ks * 16);
            cp16(sbase + o, Ah + r * lda + kb + ks * 8);
            if (PASSES == 3)
                cp16(sbase + ABYTES + o, Al + r * lda + kb + ks * 8);
        }
#pragma unroll
        for (int s = 0; s < NT / 4; s++) {            // B: NT*64 chunks
            int ch = s * 256 + tid;
            int r = ch >> 2, ks = ch & 3;
            unsigned o = (unsigned)(r * 80 + ks * 16);
            cp16(sbase + 2 * ABYTES + o, Bh + r * ldb + kb + ks * 8);
            cp16(sbase + 2 * ABYTES + BBYTES + o, Bl + r * ldb + kb + ks * 8);
        }
        CP_COMMIT();
    };

    issue(0, 0);

    for (int kt = 0; kt < ktiles; kt++) {
        const int st = kt & 1;
        // Exactly one group outstanding at loop top (group kt) -> wait all.
        CP_WAIT0();
        __syncthreads();   // staging visible to all + prev chunk's consumers done
        if (kt + 1 < ktiles) issue(st ^ 1, kt + 1);   // overlaps compute below

        const unsigned sbase = uB + st * STGB;
        const unsigned uAh = sbase, uAl = sbase + ABYTES;
        const unsigned uBh = sbase + 2 * ABYTES, uBl = uBh + BBYTES;

#pragma unroll
        for (int ks = 0; ks < 2; ks++) {
            unsigned ah[2][4], al[2][4];
#pragma unroll
            for (int mt = 0; mt < 2; mt++) {
                unsigned o = aoff + mt * 16 * 80 + ks * 32;
                ldsm4(ah[mt], uAh + o);
                if (PASSES == 3) ldsm4(al[mt], uAl + o);
            }
#pragma unroll
            for (int np = 0; np < NT / 2; np++) {
                unsigned o = boff + np * 16 * 80 + ks * 32;
                unsigned bh[4], bl[4];
                ldsm4(bh, uBh + o);
                ldsm4(bl, uBl + o);
#pragma unroll
                for (int mt = 0; mt < 2; mt++) {
#pragma unroll
                    for (int sub = 0; sub < 2; sub++) {
                        float* c = acc[mt][np * 2 + sub];
                        mma_bf16(c, ah[mt], bh[sub * 2], bh[sub * 2 + 1]);
                        mma_bf16(c, ah[mt], bl[sub * 2], bl[sub * 2 + 1]);
                        if (PASSES == 3)
                            mma_bf16(c, al[mt], bh[sub * 2], bh[sub * 2 + 1]);
                    }
                }
            }
        }
    }
    __syncthreads();   // final: protect smem before epilogue reuse / exit
}

#define SMEM_NT8 (2 * (2 * 128 * 40 * 2 + 2 * 8 * 16 * 40 * 2))   // 81920
#define SMEM_NT4 (2 * (2 * 128 * 40 * 2 + 2 * 4 * 16 * 40 * 2))   // 61440

// ---------------------------------------------------------------------------
// Kernel 1: projections. z: 0=Q 1=K 2=V 3=QR 4=KR.  out head-major hi/lo bf16.
// ---------------------------------------------------------------------------
__global__ __launch_bounds__(256) void proj_mma(
    const float* __restrict__ bq, const float* __restrict__ bk,
    const float* __restrict__ bv, const float* __restrict__ bqr,
    const float* __restrict__ bkr)
{
    const int z = blockIdx.z;
    const __nv_bfloat16 *Ah, *Al;
    if (z < 3) { Ah = g_xh; Al = g_xl; } else { Ah = g_relh; Al = g_rell; }
    const __nv_bfloat16* Bh = g_Wh[z];
    const __nv_bfloat16* Bl = g_Wl[z];

    __nv_bfloat16 *Dh, *Dl; const float* bias;
    switch (z) {
        case 0:  Dh = g_qh;  Dl = g_ql;  bias = bq;  break;
        case 1:  Dh = g_kh;  Dl = g_kl;  bias = bk;  break;
        case 2:  Dh = g_vTh; Dl = g_vTl; bias = bv;  break;
        case 3:  Dh = g_qrh; Dl = g_qrl; bias = bqr; break;
        default: Dh = g_krh; Dl = g_krl; bias = bkr; break;
    }

    const int brow = blockIdx.y * 128;
    const int bcol = blockIdx.x * 128;

    float acc[2][8][4] = {};
    gemm_core<8, 3>(Ah + brow * D_, Al + brow * D_, D_,
                    Bh + bcol * D_, Bl + bcol * D_, D_, 32, acc);

    const int lane = threadIdx.x & 31, wid = threadIdx.x >> 5;
    const int wm = wid & 3, wn = wid >> 2;
    const bool vtrans = (z == 2);

#pragma unroll
    for (int mt = 0; mt < 2; mt++) {
#pragma unroll
        for (int nt = 0; nt < 8; nt++) {
            const int n = bcol + wn * 64 + nt * 8 + (lane & 3) * 2;
            const int h = n >> 6, d = n & 63;
            const float b0 = __ldg(&bias[n]), b1 = __ldg(&bias[n + 1]);
#pragma unroll
            for (int half = 0; half < 2; half++) {
                const int m = brow + wm * 32 + mt * 16 + (lane >> 2) + half * 8;
                const int bb = m >> 10, s = m & (S_ - 1);
                float v0 = acc[mt][nt][half * 2 + 0] + b0;
                float v1 = acc[mt][nt][half * 2 + 1] + b1;
                __nv_bfloat16 h0, l0, h1, l1;
                split1(v0, h0, l0); split1(v1, h1, l1);
                if (!vtrans) {
                    const int idx = ((bb * H_ + h) * S_ + s) * DH_ + d;
                    __nv_bfloat162 ph; ph.x = h0; ph.y = h1;
                    __nv_bfloat162 pl; pl.x = l0; pl.y = l1;
                    *(__nv_bfloat162*)(Dh + idx) = ph;
                    *(__nv_bfloat162*)(Dl + idx) = pl;
                } else {
                    const int idx = ((bb * H_ + h) * DH_ + d) * S_ + s;
                    Dh[idx] = h0; Dh[idx + S_] = h1;
                    Dl[idx] = l0; Dl[idx + S_] = l1;
                }
            }
        }
    }
}

// ---------------------------------------------------------------------------
// Kernel 2: score GEMMs, 2-pass. z = bh*3 + which.  K = 64.
// which==0 (c2c): fp32 out.  which==1/2 (c2p/p2c): single-bf16 out.
// ---------------------------------------------------------------------------
__global__ __launch_bounds__(256) void scores_mma()
{
    const int z = blockIdx.z;
    const int bh = z / 3;
    const int which = z - bh * 3;
    const int ho = bh * S_ * DH_;

    const __nv_bfloat16 *Ah, *Al, *Bh, *Bl;
    float* Oc = nullptr; __nv_bfloat16* Ob = nullptr;
    if (which == 0)      { Ah = g_qh + ho;  Al = g_ql + ho;  Bh = g_kh + ho;  Bl = g_kl + ho;  Oc = g_c2c + bh * SS_; }
    else if (which == 1) { Ah = g_qh + ho;  Al = g_ql + ho;  Bh = g_krh + ho; Bl = g_krl + ho; Ob = g_c2pb + bh * SS_; }
    else                 { Ah = g_qrh + ho; Al = g_qrl + ho; Bh = g_kh + ho;  Bl = g_kl + ho;  Ob = g_p2cb + bh * SS_; }

    const int brow = blockIdx.y * 128;
    const int bcol = blockIdx.x * 128;

    float acc[2][8][4] = {};
    gemm_core<8, 2>(Ah + brow * DH_, Al + brow * DH_, DH_,
                    Bh + bcol * DH_, Bl + bcol * DH_, DH_, 2, acc);

    const int lane = threadIdx.x & 31, wid = threadIdx.x >> 5;
    const int wm = wid & 3, wn = wid >> 2;
#pragma unroll
    for (int mt = 0; mt < 2; mt++) {
#pragma unroll
        for (int nt = 0; nt < 8; nt++) {
            const int n = bcol + wn * 64 + nt * 8 + (lane & 3) * 2;
#pragma unroll
            for (int half = 0; half < 2; half++) {
                const int m = brow + wm * 32 + mt * 16 + (lane >> 2) + half * 8;
                const float v0 = acc[mt][nt][half * 2];
                const float v1 = acc[mt][nt][half * 2 + 1];
                if (which == 0) {
                    *(float2*)(Oc + m * S_ + n) = make_float2(v0, v1);
                } else {
                    __nv_bfloat162 p;
                    p.x = __float2bfloat16(v0);
                    p.y = __float2bfloat16(v1);
                    *(__nv_bfloat162*)(Ob + m * S_ + n) = p;
                }
            }
        }
    }
}

// ---------------------------------------------------------------------------
// Combine: 32 x 128 tile, exact-window band staging from bf16 sources,
// float4 main loop.
// scores = (c2c + c2p[i, p(i,j)] + p2c[p(i,j), j]) / scale, + mask
// p(i,j) = clamp(i - j + 512, 0, 1023).
// c2pS[il][w]: w = 127 - jl  -> c2p[i0+il][clamp(P0+il-127+w)]
// p2cS[t][il]: t = il - jl + 127 -> p2c[clamp(P0-127+t)][j0 + il + 127 - t]
// ---------------------------------------------------------------------------
__global__ __launch_bounds__(256) void combine_kernel(const int* __restrict__ mask)
{
    const int bh = blockIdx.z;
    const int b  = bh >> 4;
    const int i0 = blockIdx.y * 32;
    const int j0 = blockIdx.x * 128;
    const int off = bh * SS_;
    const int P0 = i0 - j0 + 512;

    __shared__ float c2pS[32][132];   // pitch 132
    __shared__ float p2cS[159][33];   // pitch 33

    const int tid = threadIdx.x;

    // Stage c2p: row il needs p in [P0+il-127, P0+il]; scalar bf16, coalesced.
    {
        const int row0 = tid >> 5;          // 0..7
        const int w0   = (tid & 31) * 4;    // 0..124 step 4
#pragma unroll
        for (int rr = 0; rr < 4; rr++) {
            const int row = row0 + rr * 8;
            const __nv_bfloat16* src = g_c2pb + off + (i0 + row) * S_;
            const int pb = P0 + row - 127 + w0;
            float4 v;
            v.x = __bfloat162float(src[min(max(pb + 0, 0), S_ - 1)]);
            v.y = __bfloat162float(src[min(max(pb + 1, 0), S_ - 1)]);
            v.z = __bfloat162float(src[min(max(pb + 2, 0), S_ - 1)]);
            v.w = __bfloat162float(src[min(max(pb + 3, 0), S_ - 1)]);
            *(float4*)&c2pS[row][w0] = v;
        }
    }

    // Stage p2c: 159 t-rows x 32 slots, coalesced 32-wide per t-row (bf16).
#pragma unroll
    for (int it = 0; it < 20; it++) {
        const int seg = it * 256 + tid;
        if (seg < 159 * 32) {
            const int t  = seg >> 5;
            const int il = seg & 31;
            const int p  = min(max(P0 - 127 + t, 0), S_ - 1);
            const int j  = min(max(j0 + il + 127 - t, 0), S_ - 1);
            p2cS[t][il] = __bfloat162float(g_p2cb[off + p * S_ + j]);
        }
    }
    __syncthreads();

    const float invScale = 0.07216878364870323f;  // 1/sqrt(3*64)
    const int il = tid >> 3;
    const int jc = (tid & 7) * 4;
    float* crow = g_c2c + off + (i0 + il) * S_ + j0;
    const int* mrow = mask + b * S_ + j0;

#pragma unroll
    for (int pass = 0; pass < 4; pass++) {
        const int jl = jc + pass * 32;
        float4 c  = *(const float4*)(crow + jl);
        float4 cp = *(const float4*)&c2pS[il][124 - jl];   // reversed order
        const int tb = il - jl + 127;
        const float q0 = p2cS[tb    ][il];
        const float q1 = p2cS[tb - 1][il];
        const float q2 = p2cS[tb - 2][il];
        const float q3 = p2cS[tb - 3][il];
        const int4 mk = *(const int4*)(mrow + jl);

        float4 r;
        r.x = mk.x ? NEG_INF : (c.x + cp.w + q0) * invScale;
        r.y = mk.y ? NEG_INF : (c.y + cp.z + q1) * invScale;
        r.z = mk.z ? NEG_INF : (c.z + cp.y + q2) * invScale;
        r.w = mk.w ? NEG_INF : (c.w + cp.x + q3) * invScale;
        *(float4*)(crow + jl) = r;
    }
}

// ---------------------------------------------------------------------------
// Softmax: read fp32 scores, write probs as hi/lo bf16.
// ---------------------------------------------------------------------------
__global__ __launch_bounds__(256) void softmax_kernel()
{
    const int rowoff = blockIdx.y * SS_ + blockIdx.x * S_;
    const float* p = g_c2c + rowoff;
    const int tid = threadIdx.x;

    float4 v = *(const float4*)(p + tid * 4);
    float mx = fmaxf(fmaxf(v.x, v.y), fmaxf(v.z, v.w));
#pragma unroll
    for (int o = 16; o > 0; o >>= 1)
        mx = fmaxf(mx, __shfl_xor_sync(0xffffffffu, mx, o));

    __shared__ float smax[8], ssum[8];
    if ((tid & 31) == 0) smax[tid >> 5] = mx;
    __syncthreads();
    mx = fmaxf(fmaxf(fmaxf(smax[0], smax[1]), fmaxf(smax[2], smax[3])),
               fmaxf(fmaxf(smax[4], smax[5]), fmaxf(smax[6], smax[7])));

    v.x = __expf(v.x - mx);
    v.y = __expf(v.y - mx);
    v.z = __expf(v.z - mx);
    v.w = __expf(v.w - mx);
    float s = v.x + v.y + v.z + v.w;
#pragma unroll
    for (int o = 16; o > 0; o >>= 1)
        s += __shfl_xor_sync(0xffffffffu, s, o);
    if ((tid & 31) == 0) ssum[tid >> 5] = s;
    __syncthreads();
    s = ssum[0] + ssum[1] + ssum[2] + ssum[3] +
        ssum[4] + ssum[5] + ssum[6] + ssum[7];

    const float inv = 1.0f / s;
    v.x *= inv; v.y *= inv; v.z *= inv; v.w *= inv;

    __nv_bfloat16 h[4], l[4];
    split1(v.x, h[0], l[0]); split1(v.y, h[1], l[1]);
    split1(v.z, h[2], l[2]); split1(v.w, h[3], l[3]);
    *(uint2*)(g_ph + rowoff + tid * 4) = *(uint2*)h;
    *(uint2*)(g_pl + rowoff + tid * 4) = *(uint2*)l;
}

// ---------------------------------------------------------------------------
// Kernel 3: attn @ V  (probs 1024x1024 @ V 1024x64 per bh) -> ctx hi/lo bf16
// ---------------------------------------------------------------------------
__global__ __launch_bounds__(256) void av_mma()
{
    const int bh = blockIdx.y;
    const int i0 = blockIdx.x * 128;
    const __nv_bfloat16* Ah = g_ph + bh * SS_ + i0 * S_;
    const __nv_bfloat16* Al = g_pl + bh * SS_ + i0 * S_;
    const __nv_bfloat16* Bh = g_vTh + bh * DH_ * S_;
    const __nv_bfloat16* Bl = g_vTl + bh * DH_ * S_;

    float acc[2][4][4] = {};
    gemm_core<4, 3>(Ah, Al, S_, Bh, Bl, S_, 32, acc);

    const int lane = threadIdx.x & 31, wid = threadIdx.x >> 5;
    const int wm = wid & 3, wn = wid >> 2;
    const int b = bh >> 4, h = bh & 15;

#pragma unroll
    for (int mt = 0; mt < 2; mt++) {
#pragma unroll
        for (int nt = 0; nt < 4; nt++) {
            const int d = wn * 32 + nt * 8 + (lane & 3) * 2;
#pragma unroll
            for (int half = 0; half < 2; half++) {
                const int s = i0 + wm * 32 + mt * 16 + (lane >> 2) + half * 8;
                const int idx = (b * S_ + s) * D_ + h * DH_ + d;
                float v0 = acc[mt][nt][half * 2 + 0];
                float v1 = acc[mt][nt][half * 2 + 1];
                __nv_bfloat16 h0, l0, h1, l1;
                split1(v0, h0, l0); split1(v1, h1, l1);
                __nv_bfloat162 ph; ph.x = h0; ph.y = h1;
                __nv_bfloat162 pl; pl.x = l0; pl.y = l1;
                *(__nv_bfloat162*)(g_ctxh + idx) = ph;
                *(__nv_bfloat162*)(g_ctxl + idx) = pl;
            }
        }
    }
}

// ---------------------------------------------------------------------------
// Kernel 4: output projection out = ctx @ Wc^T + bc  (fp32 out)
// ---------------------------------------------------------------------------
__global__ __launch_bounds__(256) void final_mma(
    const float* __restrict__ bc, float* __restrict__ out)
{
    const int brow = blockIdx.y * 128;
    const int bcol = blockIdx.x * 128;

    float acc[2][8][4] = {};
    gemm_core<8, 3>(g_ctxh + brow * D_, g_ctxl + brow * D_, D_,
                    g_Wh[5] + bcol * D_, g_Wl[5] + bcol * D_, D_, 32, acc);

    const int lane = threadIdx.x & 31, wid = threadIdx.x >> 5;
    const int wm = wid & 3, wn = wid >> 2;
#pragma unroll
    for (int mt = 0; mt < 2; mt++) {
#pragma unroll
        for (int nt = 0; nt < 8; nt++) {
            const int n = bcol + wn * 64 + nt * 8 + (lane & 3) * 2;
            const float b0 = __ldg(&bc[n]), b1 = __ldg(&bc[n + 1]);
#pragma unroll
            for (int half = 0; half < 2; half++) {
                const int m = brow + wm * 32 + mt * 16 + (lane >> 2) + half * 8;
                *(float2*)(out + m * D_ + n) =
                    make_float2(acc[mt][nt][half * 2] + b0,
                                acc[mt][nt][half * 2 + 1] + b1);
            }
        }
    }
}

// ---------------------------------------------------------------------------
// Launch
// ---------------------------------------------------------------------------
extern "C" void kernel_launch(void* const* d_in, const int* in_sizes, int n_in,
                              void* d_out, int out_size)
{
    const float* x    = (const float*)d_in[0];
    const float* rel  = (const float*)d_in[1];
    const int*   mask = (const int*)  d_in[2];
    const float* Wq   = (const float*)d_in[3];
    const float* bq   = (const float*)d_in[4];
    const float* Wk   = (const float*)d_in[5];
    const float* bk   = (const float*)d_in[6];
    const float* Wv   = (const float*)d_in[7];
    const float* bv   = (const float*)d_in[8];
    const float* Wqr  = (const float*)d_in[9];
    const float* bqr  = (const float*)d_in[10];
    const float* Wkr  = (const float*)d_in[11];
    const float* bkr  = (const float*)d_in[12];
    const float* Wc   = (const float*)d_in[13];
    const float* bc   = (const float*)d_in[14];
    float* out = (float*)d_out;

    static int attr_done = 0;
    if (!attr_done) {
        cudaFuncSetAttribute(proj_mma,   cudaFuncAttributeMaxDynamicSharedMemorySize, SMEM_NT8);
        cudaFuncSetAttribute(scores_mma, cudaFuncAttributeMaxDynamicSharedMemorySize, SMEM_NT8);
        cudaFuncSetAttribute(av_mma,     cudaFuncAttributeMaxDynamicSharedMemorySize, SMEM_NT4);
        cudaFuncSetAttribute(final_mma,  cudaFuncAttributeMaxDynamicSharedMemorySize, SMEM_NT8);
        attr_done = 1;
    }

    // 0. Split fp32 operands into hi/lo bf16 (single launch)
    convert_all<<<2621440 / 256, 256>>>(x, rel, Wq, Wk, Wv, Wqr, Wkr, Wc);

    // 1. Projections (HMMA bf16x3, z-fused)
    proj_mma<<<dim3(D_ / 128, ROWS_ / 128, 5), 256, SMEM_NT8>>>(bq, bk, bv, bqr, bkr);

    // 2. Score GEMMs (bf16x2 2-pass; c2c fp32, c2p/p2c bf16)
    scores_mma<<<dim3(S_ / 128, S_ / 128, BH_ * 3), 256, SMEM_NT8>>>();

    // 3. Banded gather + sum + scale + mask (bf16 band inputs)
    combine_kernel<<<dim3(S_ / 128, S_ / 32, BH_), 256>>>(mask);

    // 4. Softmax -> probs hi/lo bf16
    softmax_kernel<<<dim3(S_, BH_), 256>>>();

    // 5. attn @ V -> ctx hi/lo bf16 (bf16x3)
    av_mma<<<dim3(S_ / 128, BH_), 256, SMEM_NT4>>>();

    // 6. Output projection (bf16x3)
    final_mma<<<dim3(D_ / 128, ROWS_ / 128), 256, SMEM_NT8>>>(bc, out);
}